// round 2
// baseline (speedup 1.0000x reference)
#include <cuda_runtime.h>
#include <math.h>

// Problem dims
#define BQ 8
#define SQ 512
#define HQ 768
#define EQ 8
#define FQ 3072
#define KQ 2

// GEMM tiling
#define BM 128
#define BN 128
#define BK 8

// Scratch / routing state (static device memory: allocation-free, graph-safe)
__device__ float g_xbar[BQ][HQ];
__device__ float g_h[BQ * KQ][SQ][FQ];   // gelu(x@W1+b1) for the 16 selected (b,k) pairs (~100 MB)
__device__ int   g_sel[BQ][KQ];
__device__ float g_wsel[BQ][KQ];

// ---------------------------------------------------------------------------
// Mean over sequence: g_xbar[b][h] = (1/S) * sum_s x[b,s,h]
// ---------------------------------------------------------------------------
__global__ void xbar_kernel(const float* __restrict__ x) {
    int b = blockIdx.x;
    int h = threadIdx.x;
    const float* p = x + (size_t)b * SQ * HQ + h;
    float s = 0.f;
#pragma unroll 8
    for (int i = 0; i < SQ; i++) s += p[(size_t)i * HQ];
    g_xbar[b][h] = s * (1.0f / SQ);
}

// ---------------------------------------------------------------------------
// Router: logits[b,e] = xbar[b] . Wg[:,e]; softmax over E; top-2 select.
// Writes router_logits to the tail of d_out, selection to device globals.
// ---------------------------------------------------------------------------
__global__ void router_kernel(const float* __restrict__ Wg,
                              float* __restrict__ out_logits) {
    __shared__ float lg[BQ][EQ];
    int t = threadIdx.x;
    if (t < BQ * EQ) {
        int b = t / EQ, e = t % EQ;
        float s = 0.f;
        for (int h = 0; h < HQ; h++) s += g_xbar[b][h] * Wg[h * EQ + e];
        lg[b][e] = s;
        out_logits[b * EQ + e] = s;
    }
    __syncthreads();
    if (t < BQ) {
        int b = t;
        float m = -1e30f;
        for (int e = 0; e < EQ; e++) m = fmaxf(m, lg[b][e]);
        float w[EQ];
        float s = 0.f;
        for (int e = 0; e < EQ; e++) { w[e] = expf(lg[b][e] - m); s += w[e]; }
        float inv = 1.f / s;
        for (int e = 0; e < EQ; e++) w[e] *= inv;
        // top-2, first-index-wins on ties (matches lax.top_k ordering)
        int i1 = 0;
        for (int e = 1; e < EQ; e++) if (w[e] > w[i1]) i1 = e;
        int i2 = -1;
        for (int e = 0; e < EQ; e++) {
            if (e == i1) continue;
            if (i2 < 0 || w[e] > w[i2]) i2 = e;
        }
        g_sel[b][0] = i1;  g_sel[b][1] = i2;
        g_wsel[b][0] = w[i1]; g_wsel[b][1] = w[i2];
    }
}

// ---------------------------------------------------------------------------
// GEMM1: for pair p=(b,k), e=sel: g_h[p] = gelu_exact(x[b] @ W1[e] + b1[e])
//   A: [512,768] row-major, B: [768,3072] row-major, C: [512,3072]
// ---------------------------------------------------------------------------
__global__ __launch_bounds__(256, 2)
void gemm1_kernel(const float* __restrict__ X,
                  const float* __restrict__ W1,
                  const float* __restrict__ b1) {
    int p = blockIdx.z;
    int b = p >> 1;
    int kk = p & 1;
    int e = g_sel[b][kk];

    const float* A  = X  + (size_t)b * SQ * HQ;
    const float* Bm = W1 + (size_t)e * HQ * FQ;
    const float* bias = b1 + (size_t)e * FQ;
    float* C = &g_h[p][0][0];

    __shared__ float As[BK][BM + 4];
    __shared__ float Bs[BK][BN + 4];

    int tid = threadIdx.x;
    int tx = tid & 15, ty = tid >> 4;
    int m0 = blockIdx.y * BM, n0 = blockIdx.x * BN;
    int arow = tid >> 1,  ac4 = (tid & 1) * 4;
    int brow = tid >> 5,  bc4 = (tid & 31) * 4;

    float acc[8][8];
#pragma unroll
    for (int i = 0; i < 8; i++)
#pragma unroll
        for (int j = 0; j < 8; j++) acc[i][j] = 0.f;

    for (int k0 = 0; k0 < HQ; k0 += BK) {
        float4 a4 = *(const float4*)(A  + (size_t)(m0 + arow) * HQ + k0 + ac4);
        float4 b4 = *(const float4*)(Bm + (size_t)(k0 + brow) * FQ + n0 + bc4);
        As[ac4 + 0][arow] = a4.x;
        As[ac4 + 1][arow] = a4.y;
        As[ac4 + 2][arow] = a4.z;
        As[ac4 + 3][arow] = a4.w;
        *(float4*)&Bs[brow][bc4] = b4;
        __syncthreads();
#pragma unroll
        for (int kq = 0; kq < BK; kq++) {
            float af[8], bf[8];
#pragma unroll
            for (int i = 0; i < 8; i++) af[i] = As[kq][ty * 8 + i];
#pragma unroll
            for (int j = 0; j < 8; j++) bf[j] = Bs[kq][tx * 8 + j];
#pragma unroll
            for (int i = 0; i < 8; i++)
#pragma unroll
                for (int j = 0; j < 8; j++)
                    acc[i][j] = fmaf(af[i], bf[j], acc[i][j]);
        }
        __syncthreads();
    }

    // epilogue: bias + exact GELU
#pragma unroll
    for (int i = 0; i < 8; i++) {
        int row = m0 + ty * 8 + i;
#pragma unroll
        for (int j = 0; j < 8; j++) {
            int col = n0 + tx * 8 + j;
            float v = acc[i][j] + bias[col];
            v = 0.5f * v * (1.0f + erff(v * 0.70710678118654752f));
            C[(size_t)row * FQ + col] = v;
        }
    }
}

// ---------------------------------------------------------------------------
// GEMM2: out[b] = sum_k w_k * (g_h[b,k] @ W2[e_k] + b2[e_k])
// Expert weight w folded into the A-tile load so one accumulator serves both k.
//   A: [512,3072], B: [3072,768], C: [512,768]
// ---------------------------------------------------------------------------
__global__ __launch_bounds__(256, 2)
void gemm2_kernel(const float* __restrict__ W2,
                  const float* __restrict__ b2,
                  float* __restrict__ out) {
    int b = blockIdx.z;

    __shared__ float As[BK][BM + 4];
    __shared__ float Bs[BK][BN + 4];

    int tid = threadIdx.x;
    int tx = tid & 15, ty = tid >> 4;
    int m0 = blockIdx.y * BM, n0 = blockIdx.x * BN;
    int arow = tid >> 1,  ac4 = (tid & 1) * 4;
    int brow = tid >> 5,  bc4 = (tid & 31) * 4;

    int   e0 = g_sel[b][0],  e1 = g_sel[b][1];
    float w0 = g_wsel[b][0], w1 = g_wsel[b][1];

    float acc[8][8];
#pragma unroll
    for (int i = 0; i < 8; i++)
#pragma unroll
        for (int j = 0; j < 8; j++) acc[i][j] = 0.f;

    for (int kp = 0; kp < KQ; kp++) {
        int   e = kp ? e1 : e0;
        float w = kp ? w1 : w0;
        const float* A  = &g_h[b * KQ + kp][0][0];
        const float* Bm = W2 + (size_t)e * FQ * HQ;

        for (int k0 = 0; k0 < FQ; k0 += BK) {
            float4 a4 = *(const float4*)(A  + (size_t)(m0 + arow) * FQ + k0 + ac4);
            float4 b4 = *(const float4*)(Bm + (size_t)(k0 + brow) * HQ + n0 + bc4);
            As[ac4 + 0][arow] = w * a4.x;
            As[ac4 + 1][arow] = w * a4.y;
            As[ac4 + 2][arow] = w * a4.z;
            As[ac4 + 3][arow] = w * a4.w;
            *(float4*)&Bs[brow][bc4] = b4;
            __syncthreads();
#pragma unroll
            for (int kq = 0; kq < BK; kq++) {
                float af[8], bf[8];
#pragma unroll
                for (int i = 0; i < 8; i++) af[i] = As[kq][ty * 8 + i];
#pragma unroll
                for (int j = 0; j < 8; j++) bf[j] = Bs[kq][tx * 8 + j];
#pragma unroll
                for (int i = 0; i < 8; i++)
#pragma unroll
                    for (int j = 0; j < 8; j++)
                        acc[i][j] = fmaf(af[i], bf[j], acc[i][j]);
            }
            __syncthreads();
        }
    }

    // epilogue: weighted biases, single coalesced store (d_out fully overwritten)
    float bb[8];
#pragma unroll
    for (int j = 0; j < 8; j++) {
        int col = n0 + tx * 8 + j;
        bb[j] = w0 * b2[(size_t)e0 * HQ + col] + w1 * b2[(size_t)e1 * HQ + col];
    }
#pragma unroll
    for (int i = 0; i < 8; i++) {
        int row = m0 + ty * 8 + i;
#pragma unroll
        for (int j = 0; j < 8; j++) {
            int col = n0 + tx * 8 + j;
            out[(size_t)b * SQ * HQ + (size_t)row * HQ + col] = acc[i][j] + bb[j];
        }
    }
}

// ---------------------------------------------------------------------------
// Launch: xbar -> router -> gemm1(+gelu) -> gemm2 (stream-ordered, graph-safe)
// Output layout: [ final (B*S*H) | router_logits (B*E) ]
// ---------------------------------------------------------------------------
extern "C" void kernel_launch(void* const* d_in, const int* in_sizes, int n_in,
                              void* d_out, int out_size) {
    const float* x  = (const float*)d_in[0];
    const float* Wg = (const float*)d_in[1];
    const float* W1 = (const float*)d_in[2];
    const float* b1 = (const float*)d_in[3];
    const float* W2 = (const float*)d_in[4];
    const float* b2 = (const float*)d_in[5];
    float* out = (float*)d_out;
    float* out_logits = out + (size_t)BQ * SQ * HQ;

    xbar_kernel<<<BQ, HQ>>>(x);
    router_kernel<<<1, 64>>>(Wg, out_logits);
    gemm1_kernel<<<dim3(FQ / BN, SQ / BM, BQ * KQ), 256>>>(x, W1, b1);
    gemm2_kernel<<<dim3(HQ / BN, SQ / BM, BQ), 256>>>(W2, b2, out);
}

// round 11
// speedup vs baseline: 1.0099x; 1.0099x over previous
#include <cuda_runtime.h>
#include <math.h>

// Problem dims
#define BQ 8
#define SQ 512
#define HQ 768
#define EQ 8
#define FQ 3072
#define KQ 2

// GEMM tiling (identical to validated R1)
#define BM 128
#define BN 128
#define BK 8

// Scratch / routing state (static device memory: allocation-free, graph-safe)
__device__ float g_xbar[BQ][HQ];
__device__ float g_h[BQ * KQ][SQ][FQ];   // gelu(x@W1+b1) for the 16 selected (b,k) pairs
__device__ int   g_sel[BQ][KQ];
__device__ float g_wsel[BQ][KQ];

// ---------------------------------------------------------------------------
// Packed f32x2 helpers (base-Blackwell PTX; SASS FFMA2, 2x fp32 rate)
// ---------------------------------------------------------------------------
typedef unsigned long long ull;

__device__ __forceinline__ ull pk2(float x) {
    ull r;
    asm("mov.b64 %0, {%1, %1};" : "=l"(r) : "f"(x));
    return r;
}
__device__ __forceinline__ void ffma2(ull& c, ull a, ull b) {
    asm("fma.rn.f32x2 %0, %1, %2, %0;" : "+l"(c) : "l"(a), "l"(b));
}
__device__ __forceinline__ float2 upk(ull v) {
    float2 f;
    asm("mov.b64 {%0, %1}, %2;" : "=f"(f.x), "=f"(f.y) : "l"(v));
    return f;
}
__device__ __forceinline__ float gelu_exact(float v) {
    return 0.5f * v * (1.0f + erff(v * 0.70710678118654752f));
}

// ---------------------------------------------------------------------------
// Mean over sequence: g_xbar[b][h] = (1/S) * sum_s x[b,s,h]
// ---------------------------------------------------------------------------
__global__ void xbar_kernel(const float* __restrict__ x) {
    int b = blockIdx.x;
    int h = threadIdx.x;
    const float* p = x + (size_t)b * SQ * HQ + h;
    float s = 0.f;
#pragma unroll 8
    for (int i = 0; i < SQ; i++) s += p[(size_t)i * HQ];
    g_xbar[b][h] = s * (1.0f / SQ);
}

// ---------------------------------------------------------------------------
// Router: logits[b,e] = xbar[b] . Wg[:,e]; softmax over E; top-2 select.
// ---------------------------------------------------------------------------
__global__ void router_kernel(const float* __restrict__ Wg,
                              float* __restrict__ out_logits) {
    __shared__ float lg[BQ][EQ];
    int t = threadIdx.x;
    if (t < BQ * EQ) {
        int b = t / EQ, e = t % EQ;
        float s = 0.f;
        for (int h = 0; h < HQ; h++) s += g_xbar[b][h] * Wg[h * EQ + e];
        lg[b][e] = s;
        out_logits[b * EQ + e] = s;
    }
    __syncthreads();
    if (t < BQ) {
        int b = t;
        float m = -1e30f;
        for (int e = 0; e < EQ; e++) m = fmaxf(m, lg[b][e]);
        float w[EQ];
        float s = 0.f;
        for (int e = 0; e < EQ; e++) { w[e] = expf(lg[b][e] - m); s += w[e]; }
        float inv = 1.f / s;
        for (int e = 0; e < EQ; e++) w[e] *= inv;
        int i1 = 0;
        for (int e = 1; e < EQ; e++) if (w[e] > w[i1]) i1 = e;
        int i2 = -1;
        for (int e = 0; e < EQ; e++) {
            if (e == i1) continue;
            if (i2 < 0 || w[e] > w[i2]) i2 = e;
        }
        g_sel[b][0] = i1;  g_sel[b][1] = i2;
        g_wsel[b][0] = w[i1]; g_wsel[b][1] = w[i2];
    }
}

// ---------------------------------------------------------------------------
// GEMM1: for pair p=(b,k), e=sel: g_h[p] = gelu_exact(x[b] @ W1[e] + b1[e])
//   A: [512,768] row-major, B: [768,3072] row-major, C: [512,3072]
// Inner loop on packed f32x2 (FFMA2): acc[8 rows][4 col-pairs].
// ---------------------------------------------------------------------------
__global__ void __launch_bounds__(256, 2)
gemm1_kernel(const float* __restrict__ X,
             const float* __restrict__ W1,
             const float* __restrict__ b1) {
    int p = blockIdx.z;
    int b = p >> 1;
    int kk = p & 1;
    int e = g_sel[b][kk];

    const float* A  = X  + (size_t)b * SQ * HQ;
    const float* Bm = W1 + (size_t)e * HQ * FQ;
    const float* bias = b1 + (size_t)e * FQ;
    float* C = &g_h[p][0][0];

    __shared__ float As[BK][BM + 4];
    __shared__ float Bs[BK][BN + 4];

    int tid = threadIdx.x;
    int tx = tid & 15, ty = tid >> 4;
    int m0 = blockIdx.y * BM, n0 = blockIdx.x * BN;
    int arow = tid >> 1,  ac4 = (tid & 1) * 4;
    int brow = tid >> 5,  bc4 = (tid & 31) * 4;

    ull acc[8][4];
    const ull z = pk2(0.f);
#pragma unroll
    for (int i = 0; i < 8; i++)
#pragma unroll
        for (int j = 0; j < 4; j++) acc[i][j] = z;

    for (int k0 = 0; k0 < HQ; k0 += BK) {
        float4 a4 = *(const float4*)(A  + (size_t)(m0 + arow) * HQ + k0 + ac4);
        float4 b4 = *(const float4*)(Bm + (size_t)(k0 + brow) * FQ + n0 + bc4);
        As[ac4 + 0][arow] = a4.x;
        As[ac4 + 1][arow] = a4.y;
        As[ac4 + 2][arow] = a4.z;
        As[ac4 + 3][arow] = a4.w;
        *(float4*)&Bs[brow][bc4] = b4;
        __syncthreads();
#pragma unroll
        for (int kq = 0; kq < BK; kq++) {
            float4 a0 = *(const float4*)&As[kq][ty * 8];
            float4 a1 = *(const float4*)&As[kq][ty * 8 + 4];
            ulonglong2 bv0 = *(const ulonglong2*)&Bs[kq][tx * 8];
            ulonglong2 bv1 = *(const ulonglong2*)&Bs[kq][tx * 8 + 4];
            ull aa[8], bb[4];
            aa[0] = pk2(a0.x); aa[1] = pk2(a0.y); aa[2] = pk2(a0.z); aa[3] = pk2(a0.w);
            aa[4] = pk2(a1.x); aa[5] = pk2(a1.y); aa[6] = pk2(a1.z); aa[7] = pk2(a1.w);
            bb[0] = bv0.x; bb[1] = bv0.y; bb[2] = bv1.x; bb[3] = bv1.y;
#pragma unroll
            for (int i = 0; i < 8; i++)
#pragma unroll
                for (int j = 0; j < 4; j++)
                    ffma2(acc[i][j], aa[i], bb[j]);
        }
        __syncthreads();
    }

    // epilogue: bias + exact GELU
#pragma unroll
    for (int i = 0; i < 8; i++) {
        int row = m0 + ty * 8 + i;
#pragma unroll
        for (int j = 0; j < 4; j++) {
            int col = n0 + tx * 8 + j * 2;
            float2 v = upk(acc[i][j]);
            v.x = gelu_exact(v.x + bias[col]);
            v.y = gelu_exact(v.y + bias[col + 1]);
            *(float2*)&C[(size_t)row * FQ + col] = v;
        }
    }
}

// ---------------------------------------------------------------------------
// GEMM2: out[b] = sum_k w_k * (g_h[b,k] @ W2[e_k] + b2[e_k])
// Expert weight w folded into the A-tile load so one accumulator serves both k.
//   A: [512,3072], B: [3072,768], C: [512,768]
// ---------------------------------------------------------------------------
__global__ void __launch_bounds__(256, 2)
gemm2_kernel(const float* __restrict__ W2,
             const float* __restrict__ b2,
             float* __restrict__ out) {
    int b = blockIdx.z;

    __shared__ float As[BK][BM + 4];
    __shared__ float Bs[BK][BN + 4];

    int tid = threadIdx.x;
    int tx = tid & 15, ty = tid >> 4;
    int m0 = blockIdx.y * BM, n0 = blockIdx.x * BN;
    int arow = tid >> 1,  ac4 = (tid & 1) * 4;
    int brow = tid >> 5,  bc4 = (tid & 31) * 4;

    int   e0 = g_sel[b][0],  e1 = g_sel[b][1];
    float w0 = g_wsel[b][0], w1 = g_wsel[b][1];

    ull acc[8][4];
    const ull z = pk2(0.f);
#pragma unroll
    for (int i = 0; i < 8; i++)
#pragma unroll
        for (int j = 0; j < 4; j++) acc[i][j] = z;

    for (int kp = 0; kp < KQ; kp++) {
        int   e = kp ? e1 : e0;
        float w = kp ? w1 : w0;
        const float* A  = &g_h[b * KQ + kp][0][0];
        const float* Bm = W2 + (size_t)e * FQ * HQ;

        for (int k0 = 0; k0 < FQ; k0 += BK) {
            float4 a4 = *(const float4*)(A  + (size_t)(m0 + arow) * FQ + k0 + ac4);
            float4 b4 = *(const float4*)(Bm + (size_t)(k0 + brow) * HQ + n0 + bc4);
            As[ac4 + 0][arow] = w * a4.x;
            As[ac4 + 1][arow] = w * a4.y;
            As[ac4 + 2][arow] = w * a4.z;
            As[ac4 + 3][arow] = w * a4.w;
            *(float4*)&Bs[brow][bc4] = b4;
            __syncthreads();
#pragma unroll
            for (int kq = 0; kq < BK; kq++) {
                float4 a0 = *(const float4*)&As[kq][ty * 8];
                float4 a1 = *(const float4*)&As[kq][ty * 8 + 4];
                ulonglong2 bv0 = *(const ulonglong2*)&Bs[kq][tx * 8];
                ulonglong2 bv1 = *(const ulonglong2*)&Bs[kq][tx * 8 + 4];
                ull aa[8], bb[4];
                aa[0] = pk2(a0.x); aa[1] = pk2(a0.y); aa[2] = pk2(a0.z); aa[3] = pk2(a0.w);
                aa[4] = pk2(a1.x); aa[5] = pk2(a1.y); aa[6] = pk2(a1.z); aa[7] = pk2(a1.w);
                bb[0] = bv0.x; bb[1] = bv0.y; bb[2] = bv1.x; bb[3] = bv1.y;
#pragma unroll
                for (int i = 0; i < 8; i++)
#pragma unroll
                    for (int j = 0; j < 4; j++)
                        ffma2(acc[i][j], aa[i], bb[j]);
            }
            __syncthreads();
        }
    }

    // epilogue: weighted biases, coalesced float2 stores (d_out fully overwritten)
    float bb2[4][2];
#pragma unroll
    for (int j = 0; j < 4; j++) {
        int col = n0 + tx * 8 + j * 2;
        bb2[j][0] = w0 * b2[(size_t)e0 * HQ + col]     + w1 * b2[(size_t)e1 * HQ + col];
        bb2[j][1] = w0 * b2[(size_t)e0 * HQ + col + 1] + w1 * b2[(size_t)e1 * HQ + col + 1];
    }
#pragma unroll
    for (int i = 0; i < 8; i++) {
        int row = m0 + ty * 8 + i;
#pragma unroll
        for (int j = 0; j < 4; j++) {
            int col = n0 + tx * 8 + j * 2;
            float2 v = upk(acc[i][j]);
            v.x += bb2[j][0];
            v.y += bb2[j][1];
            *(float2*)&out[(size_t)b * SQ * HQ + (size_t)row * HQ + col] = v;
        }
    }
}

// ---------------------------------------------------------------------------
// Launch: xbar -> router -> gemm1(+gelu) -> gemm2 (stream-ordered, graph-safe)
// Output layout: [ final (B*S*H) | router_logits (B*E) ]
// ---------------------------------------------------------------------------
extern "C" void kernel_launch(void* const* d_in, const int* in_sizes, int n_in,
                              void* d_out, int out_size) {
    const float* x  = (const float*)d_in[0];
    const float* Wg = (const float*)d_in[1];
    const float* W1 = (const float*)d_in[2];
    const float* b1 = (const float*)d_in[3];
    const float* W2 = (const float*)d_in[4];
    const float* b2 = (const float*)d_in[5];
    float* out = (float*)d_out;
    float* out_logits = out + (size_t)BQ * SQ * HQ;

    xbar_kernel<<<BQ, HQ>>>(x);
    router_kernel<<<1, 64>>>(Wg, out_logits);
    gemm1_kernel<<<dim3(FQ / BN, SQ / BM, BQ * KQ), 256>>>(x, W1, b1);
    gemm2_kernel<<<dim3(HQ / BN, SQ / BM, BQ), 256>>>(W2, b2, out);
}

// round 12
// speedup vs baseline: 1.2200x; 1.2080x over previous
#include <cuda_runtime.h>
#include <math.h>

// Problem dims
#define BQ 8
#define SQ 512
#define HQ 768
#define EQ 8
#define FQ 3072
#define KQ 2

// GEMM tiling (validated R1 microtile)
#define BM 128
#define BN 128
#define BK 8

// Scratch / routing state (static device memory: allocation-free, graph-safe)
__device__ float g_xbar[BQ][HQ];
__device__ float g_h[BQ * KQ][SQ][FQ];      // gelu(x@W1+b1) for the 16 selected pairs
__device__ float g_part[BQ][4][SQ][HQ];     // split-K partials for gemm2 (~50 MB)
__device__ int   g_sel[BQ][KQ];
__device__ float g_wsel[BQ][KQ];

__device__ __forceinline__ float gelu_exact(float v) {
    return 0.5f * v * (1.0f + erff(v * 0.70710678118654752f));
}

// ---------------------------------------------------------------------------
// Mean over sequence: g_xbar[b][h] = (1/S) * sum_s x[b,s,h]
// ---------------------------------------------------------------------------
__global__ void xbar_kernel(const float* __restrict__ x) {
    int b = blockIdx.x;
    int h = threadIdx.x;
    const float* p = x + (size_t)b * SQ * HQ + h;
    float s = 0.f;
#pragma unroll 8
    for (int i = 0; i < SQ; i++) s += p[(size_t)i * HQ];
    g_xbar[b][h] = s * (1.0f / SQ);
}

// ---------------------------------------------------------------------------
// Router: logits[b,e] = xbar[b] . Wg[:,e]; softmax over E; top-2 select.
// ---------------------------------------------------------------------------
__global__ void router_kernel(const float* __restrict__ Wg,
                              float* __restrict__ out_logits) {
    __shared__ float lg[BQ][EQ];
    int t = threadIdx.x;
    if (t < BQ * EQ) {
        int b = t / EQ, e = t % EQ;
        float s = 0.f;
        for (int h = 0; h < HQ; h++) s += g_xbar[b][h] * Wg[h * EQ + e];
        lg[b][e] = s;
        out_logits[b * EQ + e] = s;
    }
    __syncthreads();
    if (t < BQ) {
        int b = t;
        float m = -1e30f;
        for (int e = 0; e < EQ; e++) m = fmaxf(m, lg[b][e]);
        float w[EQ];
        float s = 0.f;
        for (int e = 0; e < EQ; e++) { w[e] = expf(lg[b][e] - m); s += w[e]; }
        float inv = 1.f / s;
        for (int e = 0; e < EQ; e++) w[e] *= inv;
        int i1 = 0;
        for (int e = 1; e < EQ; e++) if (w[e] > w[i1]) i1 = e;
        int i2 = -1;
        for (int e = 0; e < EQ; e++) {
            if (e == i1) continue;
            if (i2 < 0 || w[e] > w[i2]) i2 = e;
        }
        g_sel[b][0] = i1;  g_sel[b][1] = i2;
        g_wsel[b][0] = w[i1]; g_wsel[b][1] = w[i2];
    }
}

// ---------------------------------------------------------------------------
// GEMM1: for pair p=(b,k), e=sel: g_h[p] = gelu_exact(x[b] @ W1[e] + b1[e])
//   A: [512,768], B: [768,3072], C: [512,3072]. Double-buffered smem,
//   one __syncthreads per K-tile, global prefetch overlapped with compute.
// ---------------------------------------------------------------------------
__global__ void __launch_bounds__(256, 2)
gemm1_kernel(const float* __restrict__ X,
             const float* __restrict__ W1,
             const float* __restrict__ b1) {
    int p = blockIdx.z;
    int b = p >> 1;
    int kk = p & 1;
    int e = g_sel[b][kk];

    const float* A  = X  + (size_t)b * SQ * HQ;
    const float* Bm = W1 + (size_t)e * HQ * FQ;
    const float* bias = b1 + (size_t)e * FQ;
    float* C = &g_h[p][0][0];

    __shared__ float As[2][BK][BM + 4];
    __shared__ float Bs[2][BK][BN + 4];

    int tid = threadIdx.x;
    int tx = tid & 15, ty = tid >> 4;
    int m0 = blockIdx.y * BM, n0 = blockIdx.x * BN;
    int arow = tid >> 1,  ac4 = (tid & 1) * 4;
    int brow = tid >> 5,  bc4 = (tid & 31) * 4;

    float acc[8][8];
#pragma unroll
    for (int i = 0; i < 8; i++)
#pragma unroll
        for (int j = 0; j < 8; j++) acc[i][j] = 0.f;

    // prologue: tile 0 -> buf 0
    {
        float4 a4 = *(const float4*)(A  + (size_t)(m0 + arow) * HQ + ac4);
        float4 b4 = *(const float4*)(Bm + (size_t)brow * FQ + n0 + bc4);
        As[0][ac4 + 0][arow] = a4.x;
        As[0][ac4 + 1][arow] = a4.y;
        As[0][ac4 + 2][arow] = a4.z;
        As[0][ac4 + 3][arow] = a4.w;
        *(float4*)&Bs[0][brow][bc4] = b4;
    }
    __syncthreads();

    int buf = 0;
    for (int k0 = 0; k0 < HQ; k0 += BK) {
        float4 na, nb;
        const bool more = (k0 + BK) < HQ;
        if (more) {
            na = *(const float4*)(A  + (size_t)(m0 + arow) * HQ + k0 + BK + ac4);
            nb = *(const float4*)(Bm + (size_t)(k0 + BK + brow) * FQ + n0 + bc4);
        }
#pragma unroll
        for (int kq = 0; kq < BK; kq++) {
            float af[8], bf[8];
#pragma unroll
            for (int i = 0; i < 8; i++) af[i] = As[buf][kq][ty * 8 + i];
#pragma unroll
            for (int j = 0; j < 8; j++) bf[j] = Bs[buf][kq][tx * 8 + j];
#pragma unroll
            for (int i = 0; i < 8; i++)
#pragma unroll
                for (int j = 0; j < 8; j++)
                    acc[i][j] = fmaf(af[i], bf[j], acc[i][j]);
        }
        if (more) {
            As[buf ^ 1][ac4 + 0][arow] = na.x;
            As[buf ^ 1][ac4 + 1][arow] = na.y;
            As[buf ^ 1][ac4 + 2][arow] = na.z;
            As[buf ^ 1][ac4 + 3][arow] = na.w;
            *(float4*)&Bs[buf ^ 1][brow][bc4] = nb;
            __syncthreads();
            buf ^= 1;
        }
    }

    // epilogue: bias + exact GELU
#pragma unroll
    for (int i = 0; i < 8; i++) {
        int row = m0 + ty * 8 + i;
#pragma unroll
        for (int j = 0; j < 8; j++) {
            int col = n0 + tx * 8 + j;
            float v = acc[i][j] + bias[col];
            v = 0.5f * v * (1.0f + erff(v * 0.70710678118654752f));
            C[(size_t)row * FQ + col] = v;
        }
    }
}

// ---------------------------------------------------------------------------
// GEMM2 split-K: partial q=(ex,khalf) for batch b:
//   g_part[b][q] = w_ex * ( g_h[b,ex][:, kr] @ W2[e_ex][kr, :] )
// grid z = BQ*4 -> 768 CTAs (fills the chip; gemm2 was 192-CTA bound before).
// ---------------------------------------------------------------------------
__global__ void __launch_bounds__(256, 2)
gemm2p_kernel(const float* __restrict__ W2) {
    int z = blockIdx.z;
    int b = z >> 2;
    int q = z & 3;
    int ex = q & 1;
    int khalf = q >> 1;
    const int KH = FQ / 2;                 // 1536
    const int kbase = khalf * KH;

    int   e = g_sel[b][ex];
    float w = g_wsel[b][ex];
    const float* A  = &g_h[b * KQ + ex][0][0];          // [512, FQ]
    const float* Bm = W2 + (size_t)e * FQ * HQ;          // [FQ, HQ]

    __shared__ float As[2][BK][BM + 4];
    __shared__ float Bs[2][BK][BN + 4];

    int tid = threadIdx.x;
    int tx = tid & 15, ty = tid >> 4;
    int m0 = blockIdx.y * BM, n0 = blockIdx.x * BN;
    int arow = tid >> 1,  ac4 = (tid & 1) * 4;
    int brow = tid >> 5,  bc4 = (tid & 31) * 4;

    float acc[8][8];
#pragma unroll
    for (int i = 0; i < 8; i++)
#pragma unroll
        for (int j = 0; j < 8; j++) acc[i][j] = 0.f;

    // prologue
    {
        float4 a4 = *(const float4*)(A  + (size_t)(m0 + arow) * FQ + kbase + ac4);
        float4 b4 = *(const float4*)(Bm + (size_t)(kbase + brow) * HQ + n0 + bc4);
        As[0][ac4 + 0][arow] = a4.x;
        As[0][ac4 + 1][arow] = a4.y;
        As[0][ac4 + 2][arow] = a4.z;
        As[0][ac4 + 3][arow] = a4.w;
        *(float4*)&Bs[0][brow][bc4] = b4;
    }
    __syncthreads();

    int buf = 0;
    for (int k0 = 0; k0 < KH; k0 += BK) {
        float4 na, nb;
        const bool more = (k0 + BK) < KH;
        if (more) {
            na = *(const float4*)(A  + (size_t)(m0 + arow) * FQ + kbase + k0 + BK + ac4);
            nb = *(const float4*)(Bm + (size_t)(kbase + k0 + BK + brow) * HQ + n0 + bc4);
        }
#pragma unroll
        for (int kq = 0; kq < BK; kq++) {
            float af[8], bf[8];
#pragma unroll
            for (int i = 0; i < 8; i++) af[i] = As[buf][kq][ty * 8 + i];
#pragma unroll
            for (int j = 0; j < 8; j++) bf[j] = Bs[buf][kq][tx * 8 + j];
#pragma unroll
            for (int i = 0; i < 8; i++)
#pragma unroll
                for (int j = 0; j < 8; j++)
                    acc[i][j] = fmaf(af[i], bf[j], acc[i][j]);
        }
        if (more) {
            As[buf ^ 1][ac4 + 0][arow] = na.x;
            As[buf ^ 1][ac4 + 1][arow] = na.y;
            As[buf ^ 1][ac4 + 2][arow] = na.z;
            As[buf ^ 1][ac4 + 3][arow] = na.w;
            *(float4*)&Bs[buf ^ 1][brow][bc4] = nb;
            __syncthreads();
            buf ^= 1;
        }
    }

    // epilogue: weighted partial, coalesced stores
    float* P = &g_part[b][q][0][0];
#pragma unroll
    for (int i = 0; i < 8; i++) {
        int row = m0 + ty * 8 + i;
#pragma unroll
        for (int j = 0; j < 8; j += 2) {
            int col = n0 + tx * 8 + j;
            float2 v = make_float2(w * acc[i][j], w * acc[i][j + 1]);
            *(float2*)&P[(size_t)row * HQ + col] = v;
        }
    }
}

// ---------------------------------------------------------------------------
// Reduce: out = (p0+p1+p2+p3) + w0*b2[e0] + w1*b2[e1]   (fixed order, det.)
// ---------------------------------------------------------------------------
__global__ void reduce_kernel(const float* __restrict__ b2,
                              float* __restrict__ out) {
    int i4 = blockIdx.x * blockDim.x + threadIdx.x;     // over B*S*H/4
    const int per_b = SQ * HQ / 4;                      // float4 units per plane
    int b = i4 / per_b;
    int r = i4 % per_b;
    int col = (r * 4) % HQ;

    const float4* P = (const float4*)&g_part[0][0][0][0];
    size_t base = (size_t)b * 4 * per_b + r;
    float4 s0 = P[base];
    float4 s1 = P[base + per_b];
    float4 s2 = P[base + 2 * (size_t)per_b];
    float4 s3 = P[base + 3 * (size_t)per_b];

    int   e0 = g_sel[b][0],  e1 = g_sel[b][1];
    float w0 = g_wsel[b][0], w1 = g_wsel[b][1];
    const float* c0 = b2 + (size_t)e0 * HQ + col;
    const float* c1 = b2 + (size_t)e1 * HQ + col;

    float4 o;
    o.x = ((s0.x + s1.x) + (s2.x + s3.x)) + w0 * c0[0] + w1 * c1[0];
    o.y = ((s0.y + s1.y) + (s2.y + s3.y)) + w0 * c0[1] + w1 * c1[1];
    o.z = ((s0.z + s1.z) + (s2.z + s3.z)) + w0 * c0[2] + w1 * c1[2];
    o.w = ((s0.w + s1.w) + (s2.w + s3.w)) + w0 * c0[3] + w1 * c1[3];
    ((float4*)out)[i4] = o;
}

// ---------------------------------------------------------------------------
// Launch: xbar -> router -> gemm1 -> gemm2 partials -> reduce
// Output layout: [ final (B*S*H) | router_logits (B*E) ]
// ---------------------------------------------------------------------------
extern "C" void kernel_launch(void* const* d_in, const int* in_sizes, int n_in,
                              void* d_out, int out_size) {
    const float* x  = (const float*)d_in[0];
    const float* Wg = (const float*)d_in[1];
    const float* W1 = (const float*)d_in[2];
    const float* b1 = (const float*)d_in[3];
    const float* W2 = (const float*)d_in[4];
    const float* b2 = (const float*)d_in[5];
    float* out = (float*)d_out;
    float* out_logits = out + (size_t)BQ * SQ * HQ;

    xbar_kernel<<<BQ, HQ>>>(x);
    router_kernel<<<1, 64>>>(Wg, out_logits);
    gemm1_kernel<<<dim3(FQ / BN, SQ / BM, BQ * KQ), 256>>>(x, W1, b1);
    gemm2p_kernel<<<dim3(HQ / BN, SQ / BM, BQ * 4), 256>>>(W2);
    reduce_kernel<<<(BQ * SQ * HQ / 4) / 256, 256>>>(b2, out);
}

// round 13
// speedup vs baseline: 1.2846x; 1.0529x over previous
#include <cuda_runtime.h>
#include <math.h>

// Problem dims
#define BQ 8
#define SQ 512
#define HQ 768
#define EQ 8
#define FQ 3072
#define KQ 2

// GEMM tiling (validated microtile)
#define BM 128
#define BN 128
#define BK 8

// K-splits
#define KS1 3              // gemm1: 768 = 3 x 256
#define KH1 (HQ / KS1)     // 256
#define KS2 3              // gemm2: 3072 = 3 x 1024 (per expert)
#define KH2 (FQ / KS2)     // 1024

// Scratch / routing state (static device memory: allocation-free, graph-safe)
__device__ float g_xpart[BQ][8][HQ];                  // xbar partials
__device__ float g_xbar[BQ][HQ];
__device__ int   g_sel[BQ][KQ];
__device__ float g_wsel[BQ][KQ];
__device__ float g_h1p[BQ * KQ][KS1][SQ][FQ];         // gemm1 raw partials (~302 MB)
__device__ float g_h[BQ * KQ][SQ][FQ];                // gelu(x@W1+b1) (~100 MB)
__device__ float g_part[BQ][2 * KS2][SQ][HQ];         // gemm2 partials (~75 MB)

__device__ __forceinline__ float gelu_exact(float v) {
    return 0.5f * v * (1.0f + erff(v * 0.70710678118654752f));
}

// ---------------------------------------------------------------------------
// xbar stage 1: 64 CTAs, each sums 64 seq rows -> g_xpart[b][chunk][h]
// ---------------------------------------------------------------------------
__global__ void xbar1_kernel(const float* __restrict__ x) {
    int b = blockIdx.x >> 3;
    int c = blockIdx.x & 7;
    int h = threadIdx.x;
    const float* p = x + (size_t)b * SQ * HQ + (size_t)c * 64 * HQ + h;
    float s = 0.f;
#pragma unroll 8
    for (int i = 0; i < 64; i++) s += p[(size_t)i * HQ];
    g_xpart[b][c][h] = s;
}

// xbar stage 2: fold 8 partials
__global__ void xbar2_kernel() {
    int b = blockIdx.x;
    int h = threadIdx.x;
    float s = 0.f;
#pragma unroll
    for (int c = 0; c < 8; c++) s += g_xpart[b][c][h];
    g_xbar[b][h] = s * (1.0f / SQ);
}

// ---------------------------------------------------------------------------
// Router: logits[b,e] = xbar[b] . Wg[:,e]; softmax over E; top-2 select.
// ---------------------------------------------------------------------------
__global__ void router_kernel(const float* __restrict__ Wg,
                              float* __restrict__ out_logits) {
    __shared__ float lg[BQ][EQ];
    int t = threadIdx.x;
    if (t < BQ * EQ) {
        int b = t / EQ, e = t % EQ;
        float s = 0.f;
        for (int h = 0; h < HQ; h++) s += g_xbar[b][h] * Wg[h * EQ + e];
        lg[b][e] = s;
        out_logits[b * EQ + e] = s;
    }
    __syncthreads();
    if (t < BQ) {
        int b = t;
        float m = -1e30f;
        for (int e = 0; e < EQ; e++) m = fmaxf(m, lg[b][e]);
        float w[EQ];
        float s = 0.f;
        for (int e = 0; e < EQ; e++) { w[e] = expf(lg[b][e] - m); s += w[e]; }
        float inv = 1.f / s;
        for (int e = 0; e < EQ; e++) w[e] *= inv;
        int i1 = 0;
        for (int e = 1; e < EQ; e++) if (w[e] > w[i1]) i1 = e;
        int i2 = -1;
        for (int e = 0; e < EQ; e++) {
            if (e == i1) continue;
            if (i2 < 0 || w[e] > w[i2]) i2 = e;
        }
        g_sel[b][0] = i1;  g_sel[b][1] = i2;
        g_wsel[b][0] = w[i1]; g_wsel[b][1] = w[i2];
    }
}

// ---------------------------------------------------------------------------
// GEMM1 split-K partials: z = (pair p, qslice). K slice of x[b] @ W1[e].
// Raw fp32 partial -> g_h1p. grid 24 x 4 x 48 = 4608 CTAs (97.3% fill).
// ---------------------------------------------------------------------------
__global__ void __launch_bounds__(256, 2)
gemm1p_kernel(const float* __restrict__ X,
              const float* __restrict__ W1) {
    int z = blockIdx.z;
    int p = z / KS1;
    int q = z % KS1;
    int b = p >> 1;
    int e = g_sel[b][p & 1];
    const int kbase = q * KH1;

    const float* A  = X  + (size_t)b * SQ * HQ;
    const float* Bm = W1 + (size_t)e * HQ * FQ;

    __shared__ float As[2][BK][BM + 4];
    __shared__ float Bs[2][BK][BN + 4];

    int tid = threadIdx.x;
    int tx = tid & 15, ty = tid >> 4;
    int m0 = blockIdx.y * BM, n0 = blockIdx.x * BN;
    int arow = tid >> 1,  ac4 = (tid & 1) * 4;
    int brow = tid >> 5,  bc4 = (tid & 31) * 4;

    float acc[8][8];
#pragma unroll
    for (int i = 0; i < 8; i++)
#pragma unroll
        for (int j = 0; j < 8; j++) acc[i][j] = 0.f;

    {
        float4 a4 = *(const float4*)(A  + (size_t)(m0 + arow) * HQ + kbase + ac4);
        float4 b4 = *(const float4*)(Bm + (size_t)(kbase + brow) * FQ + n0 + bc4);
        As[0][ac4 + 0][arow] = a4.x;
        As[0][ac4 + 1][arow] = a4.y;
        As[0][ac4 + 2][arow] = a4.z;
        As[0][ac4 + 3][arow] = a4.w;
        *(float4*)&Bs[0][brow][bc4] = b4;
    }
    __syncthreads();

    int buf = 0;
    for (int k0 = 0; k0 < KH1; k0 += BK) {
        float4 na, nb;
        const bool more = (k0 + BK) < KH1;
        if (more) {
            na = *(const float4*)(A  + (size_t)(m0 + arow) * HQ + kbase + k0 + BK + ac4);
            nb = *(const float4*)(Bm + (size_t)(kbase + k0 + BK + brow) * FQ + n0 + bc4);
        }
#pragma unroll
        for (int kq = 0; kq < BK; kq++) {
            float af[8], bf[8];
#pragma unroll
            for (int i = 0; i < 8; i++) af[i] = As[buf][kq][ty * 8 + i];
#pragma unroll
            for (int j = 0; j < 8; j++) bf[j] = Bs[buf][kq][tx * 8 + j];
#pragma unroll
            for (int i = 0; i < 8; i++)
#pragma unroll
                for (int j = 0; j < 8; j++)
                    acc[i][j] = fmaf(af[i], bf[j], acc[i][j]);
        }
        if (more) {
            As[buf ^ 1][ac4 + 0][arow] = na.x;
            As[buf ^ 1][ac4 + 1][arow] = na.y;
            As[buf ^ 1][ac4 + 2][arow] = na.z;
            As[buf ^ 1][ac4 + 3][arow] = na.w;
            *(float4*)&Bs[buf ^ 1][brow][bc4] = nb;
            __syncthreads();
            buf ^= 1;
        }
    }

    float* P = &g_h1p[p][q][0][0];
#pragma unroll
    for (int i = 0; i < 8; i++) {
        int row = m0 + ty * 8 + i;
#pragma unroll
        for (int j = 0; j < 8; j += 2) {
            int col = n0 + tx * 8 + j;
            *(float2*)&P[(size_t)row * FQ + col] = make_float2(acc[i][j], acc[i][j + 1]);
        }
    }
}

// ---------------------------------------------------------------------------
// Reduce1: g_h = gelu( (p0+p1)+p2 + b1[e] )   (fixed order, deterministic)
// ---------------------------------------------------------------------------
__global__ void reduce1_kernel(const float* __restrict__ b1) {
    int i4 = blockIdx.x * blockDim.x + threadIdx.x;      // over 16*S*F/4
    const int per_p = SQ * FQ / 4;
    int p = i4 / per_p;
    int r = i4 % per_p;
    int col = (r * 4) % FQ;
    int e = g_sel[p >> 1][p & 1];

    const float4* P = (const float4*)&g_h1p[0][0][0][0];
    size_t base = (size_t)p * KS1 * per_p + r;
    float4 s0 = P[base];
    float4 s1 = P[base + per_p];
    float4 s2 = P[base + 2 * (size_t)per_p];
    const float* bi = b1 + (size_t)e * FQ + col;

    float4 o;
    o.x = gelu_exact((s0.x + s1.x) + s2.x + bi[0]);
    o.y = gelu_exact((s0.y + s1.y) + s2.y + bi[1]);
    o.z = gelu_exact((s0.z + s1.z) + s2.z + bi[2]);
    o.w = gelu_exact((s0.w + s1.w) + s2.w + bi[3]);
    ((float4*)&g_h[0][0][0])[i4] = o;
}

// ---------------------------------------------------------------------------
// GEMM2 split-K partials: q = (ex, kslice) in 0..5 per batch.
//   g_part[b][q] = w_ex * ( g_h[b,ex][:, kr] @ W2[e_ex][kr, :] )
// grid 6 x 4 x 48 = 1152 CTAs (97.3% fill).
// ---------------------------------------------------------------------------
__global__ void __launch_bounds__(256, 2)
gemm2p_kernel(const float* __restrict__ W2) {
    int z = blockIdx.z;
    int b = z / (2 * KS2);
    int q = z % (2 * KS2);
    int ex = q & 1;
    int ks = q >> 1;
    const int kbase = ks * KH2;

    int   e = g_sel[b][ex];
    float w = g_wsel[b][ex];
    const float* A  = &g_h[b * KQ + ex][0][0];
    const float* Bm = W2 + (size_t)e * FQ * HQ;

    __shared__ float As[2][BK][BM + 4];
    __shared__ float Bs[2][BK][BN + 4];

    int tid = threadIdx.x;
    int tx = tid & 15, ty = tid >> 4;
    int m0 = blockIdx.y * BM, n0 = blockIdx.x * BN;
    int arow = tid >> 1,  ac4 = (tid & 1) * 4;
    int brow = tid >> 5,  bc4 = (tid & 31) * 4;

    float acc[8][8];
#pragma unroll
    for (int i = 0; i < 8; i++)
#pragma unroll
        for (int j = 0; j < 8; j++) acc[i][j] = 0.f;

    {
        float4 a4 = *(const float4*)(A  + (size_t)(m0 + arow) * FQ + kbase + ac4);
        float4 b4 = *(const float4*)(Bm + (size_t)(kbase + brow) * HQ + n0 + bc4);
        As[0][ac4 + 0][arow] = a4.x;
        As[0][ac4 + 1][arow] = a4.y;
        As[0][ac4 + 2][arow] = a4.z;
        As[0][ac4 + 3][arow] = a4.w;
        *(float4*)&Bs[0][brow][bc4] = b4;
    }
    __syncthreads();

    int buf = 0;
    for (int k0 = 0; k0 < KH2; k0 += BK) {
        float4 na, nb;
        const bool more = (k0 + BK) < KH2;
        if (more) {
            na = *(const float4*)(A  + (size_t)(m0 + arow) * FQ + kbase + k0 + BK + ac4);
            nb = *(const float4*)(Bm + (size_t)(kbase + k0 + BK + brow) * HQ + n0 + bc4);
        }
#pragma unroll
        for (int kq = 0; kq < BK; kq++) {
            float af[8], bf[8];
#pragma unroll
            for (int i = 0; i < 8; i++) af[i] = As[buf][kq][ty * 8 + i];
#pragma unroll
            for (int j = 0; j < 8; j++) bf[j] = Bs[buf][kq][tx * 8 + j];
#pragma unroll
            for (int i = 0; i < 8; i++)
#pragma unroll
                for (int j = 0; j < 8; j++)
                    acc[i][j] = fmaf(af[i], bf[j], acc[i][j]);
        }
        if (more) {
            As[buf ^ 1][ac4 + 0][arow] = na.x;
            As[buf ^ 1][ac4 + 1][arow] = na.y;
            As[buf ^ 1][ac4 + 2][arow] = na.z;
            As[buf ^ 1][ac4 + 3][arow] = na.w;
            *(float4*)&Bs[buf ^ 1][brow][bc4] = nb;
            __syncthreads();
            buf ^= 1;
        }
    }

    float* P = &g_part[b][q][0][0];
#pragma unroll
    for (int i = 0; i < 8; i++) {
        int row = m0 + ty * 8 + i;
#pragma unroll
        for (int j = 0; j < 8; j += 2) {
            int col = n0 + tx * 8 + j;
            *(float2*)&P[(size_t)row * HQ + col] =
                make_float2(w * acc[i][j], w * acc[i][j + 1]);
        }
    }
}

// ---------------------------------------------------------------------------
// Reduce2: out = sum of 6 partials + w0*b2[e0] + w1*b2[e1]  (fixed order)
// ---------------------------------------------------------------------------
__global__ void reduce2_kernel(const float* __restrict__ b2,
                               float* __restrict__ out) {
    int i4 = blockIdx.x * blockDim.x + threadIdx.x;      // over B*S*H/4
    const int per_b = SQ * HQ / 4;
    int b = i4 / per_b;
    int r = i4 % per_b;
    int col = (r * 4) % HQ;

    const float4* P = (const float4*)&g_part[0][0][0][0];
    size_t base = (size_t)b * (2 * KS2) * per_b + r;
    float4 s0 = P[base];
    float4 s1 = P[base + per_b];
    float4 s2 = P[base + 2 * (size_t)per_b];
    float4 s3 = P[base + 3 * (size_t)per_b];
    float4 s4 = P[base + 4 * (size_t)per_b];
    float4 s5 = P[base + 5 * (size_t)per_b];

    int   e0 = g_sel[b][0],  e1 = g_sel[b][1];
    float w0 = g_wsel[b][0], w1 = g_wsel[b][1];
    const float* c0 = b2 + (size_t)e0 * HQ + col;
    const float* c1 = b2 + (size_t)e1 * HQ + col;

    float4 o;
    o.x = ((s0.x + s1.x) + (s2.x + s3.x)) + (s4.x + s5.x) + w0 * c0[0] + w1 * c1[0];
    o.y = ((s0.y + s1.y) + (s2.y + s3.y)) + (s4.y + s5.y) + w0 * c0[1] + w1 * c1[1];
    o.z = ((s0.z + s1.z) + (s2.z + s3.z)) + (s4.z + s5.z) + w0 * c0[2] + w1 * c1[2];
    o.w = ((s0.w + s1.w) + (s2.w + s3.w)) + (s4.w + s5.w) + w0 * c0[3] + w1 * c1[3];
    ((float4*)out)[i4] = o;
}

// ---------------------------------------------------------------------------
// Launch: xbar1/2 -> router -> gemm1 partials -> reduce1(+gelu)
//         -> gemm2 partials -> reduce2
// Output layout: [ final (B*S*H) | router_logits (B*E) ]
// ---------------------------------------------------------------------------
extern "C" void kernel_launch(void* const* d_in, const int* in_sizes, int n_in,
                              void* d_out, int out_size) {
    const float* x  = (const float*)d_in[0];
    const float* Wg = (const float*)d_in[1];
    const float* W1 = (const float*)d_in[2];
    const float* b1 = (const float*)d_in[3];
    const float* W2 = (const float*)d_in[4];
    const float* b2 = (const float*)d_in[5];
    float* out = (float*)d_out;
    float* out_logits = out + (size_t)BQ * SQ * HQ;

    xbar1_kernel<<<BQ * 8, HQ>>>(x);
    xbar2_kernel<<<BQ, HQ>>>();
    router_kernel<<<1, 64>>>(Wg, out_logits);
    gemm1p_kernel<<<dim3(FQ / BN, SQ / BM, BQ * KQ * KS1), 256>>>(x, W1);
    reduce1_kernel<<<(BQ * KQ * SQ * FQ / 4) / 256, 256>>>(b1);
    gemm2p_kernel<<<dim3(HQ / BN, SQ / BM, BQ * 2 * KS2), 256>>>(W2);
    reduce2_kernel<<<(BQ * SQ * HQ / 4) / 256, 256>>>(b2, out);
}

// round 14
// speedup vs baseline: 1.2980x; 1.0105x over previous
#include <cuda_runtime.h>
#include <math.h>

// Problem dims
#define BQ 8
#define SQ 512
#define HQ 768
#define EQ 8
#define FQ 3072
#define KQ 2

// GEMM tiling
#define BM 128
#define BN 128
#define BK 16

// K-splits
#define KS1 3              // gemm1: 768 = 3 x 256
#define KH1 (HQ / KS1)     // 256
#define KS2 3              // gemm2: 3072 = 3 x 1024 (per expert)
#define KH2 (FQ / KS2)     // 1024

// Scratch / routing state (static device memory: allocation-free, graph-safe)
__device__ float g_xpart[BQ][8][HQ];                  // xbar partials
__device__ float g_xbar[BQ][HQ];
__device__ int   g_sel[BQ][KQ];
__device__ float g_wsel[BQ][KQ];
__device__ float g_h1p[BQ * KQ][KS1][SQ][FQ];         // gemm1 raw partials (~302 MB)
__device__ float g_h[BQ * KQ][SQ][FQ];                // gelu(x@W1+b1) (~100 MB)
__device__ float g_part[BQ][2 * KS2][SQ][HQ];         // gemm2 partials (~75 MB)

__device__ __forceinline__ float gelu_exact(float v) {
    return 0.5f * v * (1.0f + erff(v * 0.70710678118654752f));
}
__device__ __forceinline__ void cp16(void* sdst, const void* gsrc) {
    unsigned d = (unsigned)__cvta_generic_to_shared(sdst);
    asm volatile("cp.async.cg.shared.global [%0], [%1], 16;\n" :: "r"(d), "l"(gsrc));
}
#define CP_COMMIT() asm volatile("cp.async.commit_group;\n" ::)
#define CP_WAIT0()  asm volatile("cp.async.wait_group 0;\n" ::)

// ---------------------------------------------------------------------------
// xbar stage 1: 64 CTAs, each sums 64 seq rows -> g_xpart[b][chunk][h]
// ---------------------------------------------------------------------------
__global__ void xbar1_kernel(const float* __restrict__ x) {
    int b = blockIdx.x >> 3;
    int c = blockIdx.x & 7;
    int h = threadIdx.x;
    const float* p = x + (size_t)b * SQ * HQ + (size_t)c * 64 * HQ + h;
    float s = 0.f;
#pragma unroll 8
    for (int i = 0; i < 64; i++) s += p[(size_t)i * HQ];
    g_xpart[b][c][h] = s;
}

// xbar stage 2: fold 8 partials
__global__ void xbar2_kernel() {
    int b = blockIdx.x;
    int h = threadIdx.x;
    float s = 0.f;
#pragma unroll
    for (int c = 0; c < 8; c++) s += g_xpart[b][c][h];
    g_xbar[b][h] = s * (1.0f / SQ);
}

// ---------------------------------------------------------------------------
// Router: logits[b,e] = xbar[b] . Wg[:,e]; softmax over E; top-2 select.
// ---------------------------------------------------------------------------
__global__ void router_kernel(const float* __restrict__ Wg,
                              float* __restrict__ out_logits) {
    __shared__ float lg[BQ][EQ];
    int t = threadIdx.x;
    if (t < BQ * EQ) {
        int b = t / EQ, e = t % EQ;
        float s = 0.f;
        for (int h = 0; h < HQ; h++) s += g_xbar[b][h] * Wg[h * EQ + e];
        lg[b][e] = s;
        out_logits[b * EQ + e] = s;
    }
    __syncthreads();
    if (t < BQ) {
        int b = t;
        float m = -1e30f;
        for (int e = 0; e < EQ; e++) m = fmaxf(m, lg[b][e]);
        float w[EQ];
        float s = 0.f;
        for (int e = 0; e < EQ; e++) { w[e] = expf(lg[b][e] - m); s += w[e]; }
        float inv = 1.f / s;
        for (int e = 0; e < EQ; e++) w[e] *= inv;
        int i1 = 0;
        for (int e = 1; e < EQ; e++) if (w[e] > w[i1]) i1 = e;
        int i2 = -1;
        for (int e = 0; e < EQ; e++) {
            if (e == i1) continue;
            if (i2 < 0 || w[e] > w[i2]) i2 = e;
        }
        g_sel[b][0] = i1;  g_sel[b][1] = i2;
        g_wsel[b][0] = w[i1]; g_wsel[b][1] = w[i2];
    }
}

// ---------------------------------------------------------------------------
// GEMM core macro body (BK=16): A via register double-buffer (transposed store),
// B via cp.async double-buffer. One __syncthreads per 16-deep K-tile.
// ---------------------------------------------------------------------------

// ---------------------------------------------------------------------------
// GEMM1 split-K partials: z = (pair p, qslice). K slice of x[b] @ W1[e].
// Raw fp32 partial -> g_h1p. grid 24 x 4 x 48 = 4608 CTAs (97.3% fill).
// ---------------------------------------------------------------------------
__global__ void __launch_bounds__(256, 2)
gemm1p_kernel(const float* __restrict__ X,
              const float* __restrict__ W1) {
    int z = blockIdx.z;
    int p = z / KS1;
    int q = z % KS1;
    int b = p >> 1;
    int e = g_sel[b][p & 1];
    const int kbase = q * KH1;

    const float* A  = X  + (size_t)b * SQ * HQ;
    const float* Bm = W1 + (size_t)e * HQ * FQ;

    __shared__ float As[2][BK][BM + 4];
    __shared__ float Bs[2][BK][BN + 4];

    int tid = threadIdx.x;
    int tx = tid & 15, ty = tid >> 4;
    int m0 = blockIdx.y * BM, n0 = blockIdx.x * BN;
    int arow = tid >> 1,  ac8 = (tid & 1) * 8;     // A: 1 row, 8 cols (2 float4)
    int brow = tid >> 4,  bc  = (tid & 15) * 8;    // B: 1 row, 8 cols (2 cp16)

    float acc[8][8];
#pragma unroll
    for (int i = 0; i < 8; i++)
#pragma unroll
        for (int j = 0; j < 8; j++) acc[i][j] = 0.f;

    // prologue: tile 0
    {
        const float* ap = A + (size_t)(m0 + arow) * HQ + kbase + ac8;
        float4 a0 = *(const float4*)ap;
        float4 a1 = *(const float4*)(ap + 4);
        As[0][ac8 + 0][arow] = a0.x;  As[0][ac8 + 1][arow] = a0.y;
        As[0][ac8 + 2][arow] = a0.z;  As[0][ac8 + 3][arow] = a0.w;
        As[0][ac8 + 4][arow] = a1.x;  As[0][ac8 + 5][arow] = a1.y;
        As[0][ac8 + 6][arow] = a1.z;  As[0][ac8 + 7][arow] = a1.w;
        const float* bp = Bm + (size_t)(kbase + brow) * FQ + n0 + bc;
        cp16(&Bs[0][brow][bc], bp);
        cp16(&Bs[0][brow][bc + 4], bp + 4);
        CP_COMMIT();
    }
    CP_WAIT0();
    __syncthreads();

    int buf = 0;
    const int NT = KH1 / BK;
    for (int kt = 0; kt < NT; kt++) {
        float4 na0, na1;
        const bool more = (kt + 1) < NT;
        if (more) {
            const float* ap = A + (size_t)(m0 + arow) * HQ + kbase + (kt + 1) * BK + ac8;
            na0 = *(const float4*)ap;
            na1 = *(const float4*)(ap + 4);
            const float* bp = Bm + (size_t)(kbase + (kt + 1) * BK + brow) * FQ + n0 + bc;
            cp16(&Bs[buf ^ 1][brow][bc], bp);
            cp16(&Bs[buf ^ 1][brow][bc + 4], bp + 4);
            CP_COMMIT();
        }
#pragma unroll
        for (int kq = 0; kq < BK; kq++) {
            float af[8], bf[8];
#pragma unroll
            for (int i = 0; i < 8; i++) af[i] = As[buf][kq][ty * 8 + i];
#pragma unroll
            for (int j = 0; j < 8; j++) bf[j] = Bs[buf][kq][tx * 8 + j];
#pragma unroll
            for (int i = 0; i < 8; i++)
#pragma unroll
                for (int j = 0; j < 8; j++)
                    acc[i][j] = fmaf(af[i], bf[j], acc[i][j]);
        }
        if (more) {
            As[buf ^ 1][ac8 + 0][arow] = na0.x;  As[buf ^ 1][ac8 + 1][arow] = na0.y;
            As[buf ^ 1][ac8 + 2][arow] = na0.z;  As[buf ^ 1][ac8 + 3][arow] = na0.w;
            As[buf ^ 1][ac8 + 4][arow] = na1.x;  As[buf ^ 1][ac8 + 5][arow] = na1.y;
            As[buf ^ 1][ac8 + 6][arow] = na1.z;  As[buf ^ 1][ac8 + 7][arow] = na1.w;
            CP_WAIT0();
            __syncthreads();
            buf ^= 1;
        }
    }

    float* P = &g_h1p[p][q][0][0];
#pragma unroll
    for (int i = 0; i < 8; i++) {
        int row = m0 + ty * 8 + i;
        int col = n0 + tx * 8;
        float4 v0 = make_float4(acc[i][0], acc[i][1], acc[i][2], acc[i][3]);
        float4 v1 = make_float4(acc[i][4], acc[i][5], acc[i][6], acc[i][7]);
        *(float4*)&P[(size_t)row * FQ + col]     = v0;
        *(float4*)&P[(size_t)row * FQ + col + 4] = v1;
    }
}

// ---------------------------------------------------------------------------
// Reduce1: g_h = gelu( (p0+p1)+p2 + b1[e] )   (fixed order, deterministic)
// ---------------------------------------------------------------------------
__global__ void reduce1_kernel(const float* __restrict__ b1) {
    int i4 = blockIdx.x * blockDim.x + threadIdx.x;      // over 16*S*F/4
    const int per_p = SQ * FQ / 4;
    int p = i4 / per_p;
    int r = i4 % per_p;
    int col = (r * 4) % FQ;
    int e = g_sel[p >> 1][p & 1];

    const float4* P = (const float4*)&g_h1p[0][0][0][0];
    size_t base = (size_t)p * KS1 * per_p + r;
    float4 s0 = P[base];
    float4 s1 = P[base + per_p];
    float4 s2 = P[base + 2 * (size_t)per_p];
    const float* bi = b1 + (size_t)e * FQ + col;

    float4 o;
    o.x = gelu_exact((s0.x + s1.x) + s2.x + bi[0]);
    o.y = gelu_exact((s0.y + s1.y) + s2.y + bi[1]);
    o.z = gelu_exact((s0.z + s1.z) + s2.z + bi[2]);
    o.w = gelu_exact((s0.w + s1.w) + s2.w + bi[3]);
    ((float4*)&g_h[0][0][0])[i4] = o;
}

// ---------------------------------------------------------------------------
// GEMM2 split-K partials: q = (ex, kslice) in 0..5 per batch.
//   g_part[b][q] = w_ex * ( g_h[b,ex][:, kr] @ W2[e_ex][kr, :] )
// grid 6 x 4 x 48 = 1152 CTAs (97.3% fill).
// ---------------------------------------------------------------------------
__global__ void __launch_bounds__(256, 2)
gemm2p_kernel(const float* __restrict__ W2) {
    int z = blockIdx.z;
    int b = z / (2 * KS2);
    int q = z % (2 * KS2);
    int ex = q & 1;
    int ks = q >> 1;
    const int kbase = ks * KH2;

    int   e = g_sel[b][ex];
    float w = g_wsel[b][ex];
    const float* A  = &g_h[b * KQ + ex][0][0];
    const float* Bm = W2 + (size_t)e * FQ * HQ;

    __shared__ float As[2][BK][BM + 4];
    __shared__ float Bs[2][BK][BN + 4];

    int tid = threadIdx.x;
    int tx = tid & 15, ty = tid >> 4;
    int m0 = blockIdx.y * BM, n0 = blockIdx.x * BN;
    int arow = tid >> 1,  ac8 = (tid & 1) * 8;
    int brow = tid >> 4,  bc  = (tid & 15) * 8;

    float acc[8][8];
#pragma unroll
    for (int i = 0; i < 8; i++)
#pragma unroll
        for (int j = 0; j < 8; j++) acc[i][j] = 0.f;

    // prologue: tile 0
    {
        const float* ap = A + (size_t)(m0 + arow) * FQ + kbase + ac8;
        float4 a0 = *(const float4*)ap;
        float4 a1 = *(const float4*)(ap + 4);
        As[0][ac8 + 0][arow] = a0.x;  As[0][ac8 + 1][arow] = a0.y;
        As[0][ac8 + 2][arow] = a0.z;  As[0][ac8 + 3][arow] = a0.w;
        As[0][ac8 + 4][arow] = a1.x;  As[0][ac8 + 5][arow] = a1.y;
        As[0][ac8 + 6][arow] = a1.z;  As[0][ac8 + 7][arow] = a1.w;
        const float* bp = Bm + (size_t)(kbase + brow) * HQ + n0 + bc;
        cp16(&Bs[0][brow][bc], bp);
        cp16(&Bs[0][brow][bc + 4], bp + 4);
        CP_COMMIT();
    }
    CP_WAIT0();
    __syncthreads();

    int buf = 0;
    const int NT = KH2 / BK;
    for (int kt = 0; kt < NT; kt++) {
        float4 na0, na1;
        const bool more = (kt + 1) < NT;
        if (more) {
            const float* ap = A + (size_t)(m0 + arow) * FQ + kbase + (kt + 1) * BK + ac8;
            na0 = *(const float4*)ap;
            na1 = *(const float4*)(ap + 4);
            const float* bp = Bm + (size_t)(kbase + (kt + 1) * BK + brow) * HQ + n0 + bc;
            cp16(&Bs[buf ^ 1][brow][bc], bp);
            cp16(&Bs[buf ^ 1][brow][bc + 4], bp + 4);
            CP_COMMIT();
        }
#pragma unroll
        for (int kq = 0; kq < BK; kq++) {
            float af[8], bf[8];
#pragma unroll
            for (int i = 0; i < 8; i++) af[i] = As[buf][kq][ty * 8 + i];
#pragma unroll
            for (int j = 0; j < 8; j++) bf[j] = Bs[buf][kq][tx * 8 + j];
#pragma unroll
            for (int i = 0; i < 8; i++)
#pragma unroll
                for (int j = 0; j < 8; j++)
                    acc[i][j] = fmaf(af[i], bf[j], acc[i][j]);
        }
        if (more) {
            As[buf ^ 1][ac8 + 0][arow] = na0.x;  As[buf ^ 1][ac8 + 1][arow] = na0.y;
            As[buf ^ 1][ac8 + 2][arow] = na0.z;  As[buf ^ 1][ac8 + 3][arow] = na0.w;
            As[buf ^ 1][ac8 + 4][arow] = na1.x;  As[buf ^ 1][ac8 + 5][arow] = na1.y;
            As[buf ^ 1][ac8 + 6][arow] = na1.z;  As[buf ^ 1][ac8 + 7][arow] = na1.w;
            CP_WAIT0();
            __syncthreads();
            buf ^= 1;
        }
    }

    float* P = &g_part[b][q][0][0];
#pragma unroll
    for (int i = 0; i < 8; i++) {
        int row = m0 + ty * 8 + i;
        int col = n0 + tx * 8;
        float4 v0 = make_float4(w * acc[i][0], w * acc[i][1], w * acc[i][2], w * acc[i][3]);
        float4 v1 = make_float4(w * acc[i][4], w * acc[i][5], w * acc[i][6], w * acc[i][7]);
        *(float4*)&P[(size_t)row * HQ + col]     = v0;
        *(float4*)&P[(size_t)row * HQ + col + 4] = v1;
    }
}

// ---------------------------------------------------------------------------
// Reduce2: out = sum of 6 partials + w0*b2[e0] + w1*b2[e1]  (fixed order)
// ---------------------------------------------------------------------------
__global__ void reduce2_kernel(const float* __restrict__ b2,
                               float* __restrict__ out) {
    int i4 = blockIdx.x * blockDim.x + threadIdx.x;      // over B*S*H/4
    const int per_b = SQ * HQ / 4;
    int b = i4 / per_b;
    int r = i4 % per_b;
    int col = (r * 4) % HQ;

    const float4* P = (const float4*)&g_part[0][0][0][0];
    size_t base = (size_t)b * (2 * KS2) * per_b + r;
    float4 s0 = P[base];
    float4 s1 = P[base + per_b];
    float4 s2 = P[base + 2 * (size_t)per_b];
    float4 s3 = P[base + 3 * (size_t)per_b];
    float4 s4 = P[base + 4 * (size_t)per_b];
    float4 s5 = P[base + 5 * (size_t)per_b];

    int   e0 = g_sel[b][0],  e1 = g_sel[b][1];
    float w0 = g_wsel[b][0], w1 = g_wsel[b][1];
    const float* c0 = b2 + (size_t)e0 * HQ + col;
    const float* c1 = b2 + (size_t)e1 * HQ + col;

    float4 o;
    o.x = ((s0.x + s1.x) + (s2.x + s3.x)) + (s4.x + s5.x) + w0 * c0[0] + w1 * c1[0];
    o.y = ((s0.y + s1.y) + (s2.y + s3.y)) + (s4.y + s5.y) + w0 * c0[1] + w1 * c1[1];
    o.z = ((s0.z + s1.z) + (s2.z + s3.z)) + (s4.z + s5.z) + w0 * c0[2] + w1 * c1[2];
    o.w = ((s0.w + s1.w) + (s2.w + s3.w)) + (s4.w + s5.w) + w0 * c0[3] + w1 * c1[3];
    ((float4*)out)[i4] = o;
}

// ---------------------------------------------------------------------------
// Launch: xbar1/2 -> router -> gemm1 partials -> reduce1(+gelu)
//         -> gemm2 partials -> reduce2
// Output layout: [ final (B*S*H) | router_logits (B*E) ]
// ---------------------------------------------------------------------------
extern "C" void kernel_launch(void* const* d_in, const int* in_sizes, int n_in,
                              void* d_out, int out_size) {
    const float* x  = (const float*)d_in[0];
    const float* Wg = (const float*)d_in[1];
    const float* W1 = (const float*)d_in[2];
    const float* b1 = (const float*)d_in[3];
    const float* W2 = (const float*)d_in[4];
    const float* b2 = (const float*)d_in[5];
    float* out = (float*)d_out;
    float* out_logits = out + (size_t)BQ * SQ * HQ;

    xbar1_kernel<<<BQ * 8, HQ>>>(x);
    xbar2_kernel<<<BQ, HQ>>>();
    router_kernel<<<1, 64>>>(Wg, out_logits);
    gemm1p_kernel<<<dim3(FQ / BN, SQ / BM, BQ * KQ * KS1), 256>>>(x, W1);
    reduce1_kernel<<<(BQ * KQ * SQ * FQ / 4) / 256, 256>>>(b1);
    gemm2p_kernel<<<dim3(HQ / BN, SQ / BM, BQ * 2 * KS2), 256>>>(W2);
    reduce2_kernel<<<(BQ * SQ * HQ / 4) / 256, 256>>>(b2, out);
}

// round 15
// speedup vs baseline: 1.3305x; 1.0250x over previous
#include <cuda_runtime.h>
#include <math.h>

// Problem dims
#define BQ 8
#define SQ 512
#define HQ 768
#define EQ 8
#define FQ 3072
#define KQ 2

// GEMM tiling
#define BM 128
#define BN 128
#define BK 16

// K-splits
#define KS1 3              // gemm1: 768 = 3 x 256
#define KH1 (HQ / KS1)     // 256
#define KS2 3              // gemm2: 3072 = 3 x 1024 (per expert)
#define KH2 (FQ / KS2)     // 1024

// Scratch / routing state (static device memory: allocation-free, graph-safe)
__device__ float g_xpart[BQ][8][HQ];                  // xbar partials
__device__ float g_xbar[BQ][HQ];
__device__ int   g_sel[BQ][KQ];
__device__ float g_wsel[BQ][KQ];
__device__ float g_h1p[BQ * KQ][KS1][SQ][FQ];         // gemm1 raw partials (~302 MB)
__device__ float g_h[BQ * KQ][SQ][FQ];                // gelu(x@W1+b1) (~100 MB)
__device__ float g_part[BQ][2 * KS2][SQ][HQ];         // gemm2 partials (~75 MB)

__device__ __forceinline__ float gelu_exact(float v) {
    return 0.5f * v * (1.0f + erff(v * 0.70710678118654752f));
}
__device__ __forceinline__ void cp16(void* sdst, const void* gsrc) {
    unsigned d = (unsigned)__cvta_generic_to_shared(sdst);
    asm volatile("cp.async.cg.shared.global [%0], [%1], 16;\n" :: "r"(d), "l"(gsrc));
}
#define CP_COMMIT() asm volatile("cp.async.commit_group;\n" ::)
#define CP_WAIT0()  asm volatile("cp.async.wait_group 0;\n" ::)

// ---------------------------------------------------------------------------
// xbar stage 1: 64 CTAs, each sums 64 seq rows -> g_xpart[b][chunk][h]
// ---------------------------------------------------------------------------
__global__ void xbar1_kernel(const float* __restrict__ x) {
    int b = blockIdx.x >> 3;
    int c = blockIdx.x & 7;
    int h = threadIdx.x;
    const float* p = x + (size_t)b * SQ * HQ + (size_t)c * 64 * HQ + h;
    float s = 0.f;
#pragma unroll 8
    for (int i = 0; i < 64; i++) s += p[(size_t)i * HQ];
    g_xpart[b][c][h] = s;
}

// xbar stage 2: fold 8 partials
__global__ void xbar2_kernel() {
    int b = blockIdx.x;
    int h = threadIdx.x;
    float s = 0.f;
#pragma unroll
    for (int c = 0; c < 8; c++) s += g_xpart[b][c][h];
    g_xbar[b][h] = s * (1.0f / SQ);
}

// ---------------------------------------------------------------------------
// Router: logits[b,e] = xbar[b] . Wg[:,e]; softmax over E; top-2 select.
// ---------------------------------------------------------------------------
__global__ void router_kernel(const float* __restrict__ Wg,
                              float* __restrict__ out_logits) {
    __shared__ float lg[BQ][EQ];
    int t = threadIdx.x;
    if (t < BQ * EQ) {
        int b = t / EQ, e = t % EQ;
        float s = 0.f;
        for (int h = 0; h < HQ; h++) s += g_xbar[b][h] * Wg[h * EQ + e];
        lg[b][e] = s;
        out_logits[b * EQ + e] = s;
    }
    __syncthreads();
    if (t < BQ) {
        int b = t;
        float m = -1e30f;
        for (int e = 0; e < EQ; e++) m = fmaxf(m, lg[b][e]);
        float w[EQ];
        float s = 0.f;
        for (int e = 0; e < EQ; e++) { w[e] = expf(lg[b][e] - m); s += w[e]; }
        float inv = 1.f / s;
        for (int e = 0; e < EQ; e++) w[e] *= inv;
        int i1 = 0;
        for (int e = 1; e < EQ; e++) if (w[e] > w[i1]) i1 = e;
        int i2 = -1;
        for (int e = 0; e < EQ; e++) {
            if (e == i1) continue;
            if (i2 < 0 || w[e] > w[i2]) i2 = e;
        }
        g_sel[b][0] = i1;  g_sel[b][1] = i2;
        g_wsel[b][0] = w[i1]; g_wsel[b][1] = w[i2];
    }
}

// ---------------------------------------------------------------------------
// Pipelined GEMM mainloop body (shared by both GEMM kernels).
// Software-pipelined fragments: LDS for k-step kq+1 issued before FMAs of kq.
// FR(kq) selects the register set by parity (fully unrolled -> static).
// ---------------------------------------------------------------------------
#define GEMM_MAINLOOP(Aptr, Bptr, LDA, LDB, KLEN)                                   \
    {                                                                               \
        const float* ap0 = (Aptr) + (size_t)(m0 + arow) * (LDA) + ac8;              \
        float4 a0 = *(const float4*)ap0;                                            \
        float4 a1 = *(const float4*)(ap0 + 4);                                      \
        As[0][ac8 + 0][arow] = a0.x;  As[0][ac8 + 1][arow] = a0.y;                  \
        As[0][ac8 + 2][arow] = a0.z;  As[0][ac8 + 3][arow] = a0.w;                  \
        As[0][ac8 + 4][arow] = a1.x;  As[0][ac8 + 5][arow] = a1.y;                  \
        As[0][ac8 + 6][arow] = a1.z;  As[0][ac8 + 7][arow] = a1.w;                  \
        const float* bp0 = (Bptr) + (size_t)brow * (LDB) + n0 + bc;                 \
        cp16(&Bs[0][brow][bc], bp0);                                                \
        cp16(&Bs[0][brow][bc + 4], bp0 + 4);                                        \
        CP_COMMIT();                                                                \
        CP_WAIT0();                                                                 \
        __syncthreads();                                                            \
    }                                                                               \
    int buf = 0;                                                                    \
    const int NT = (KLEN) / BK;                                                     \
    float af[2][8], bf[2][8];                                                       \
    _Pragma("unroll")                                                               \
    for (int i = 0; i < 8; i++) af[0][i] = As[0][0][ty * 8 + i];                    \
    _Pragma("unroll")                                                               \
    for (int j = 0; j < 8; j++) bf[0][j] = Bs[0][0][tx * 8 + j];                    \
    for (int kt = 0; kt < NT; kt++) {                                               \
        float4 na0, na1;                                                            \
        const bool more = (kt + 1) < NT;                                            \
        if (more) {                                                                 \
            const float* ap = (Aptr) + (size_t)(m0 + arow) * (LDA)                  \
                              + (kt + 1) * BK + ac8;                                \
            na0 = *(const float4*)ap;                                               \
            na1 = *(const float4*)(ap + 4);                                         \
            const float* bp = (Bptr) + (size_t)((kt + 1) * BK + brow) * (LDB)       \
                              + n0 + bc;                                            \
            cp16(&Bs[buf ^ 1][brow][bc], bp);                                       \
            cp16(&Bs[buf ^ 1][brow][bc + 4], bp + 4);                               \
            CP_COMMIT();                                                            \
        }                                                                           \
        _Pragma("unroll")                                                           \
        for (int kq = 0; kq < BK; kq++) {                                           \
            int cur = kq & 1, nxt = cur ^ 1;                                        \
            if (kq + 1 < BK) {                                                      \
                _Pragma("unroll")                                                   \
                for (int i = 0; i < 8; i++) af[nxt][i] = As[buf][kq + 1][ty * 8 + i];\
                _Pragma("unroll")                                                   \
                for (int j = 0; j < 8; j++) bf[nxt][j] = Bs[buf][kq + 1][tx * 8 + j];\
            }                                                                       \
            _Pragma("unroll")                                                       \
            for (int i = 0; i < 8; i++)                                             \
                _Pragma("unroll")                                                   \
                for (int j = 0; j < 8; j++)                                         \
                    acc[i][j] = fmaf(af[cur][i], bf[cur][j], acc[i][j]);            \
        }                                                                           \
        if (more) {                                                                 \
            As[buf ^ 1][ac8 + 0][arow] = na0.x;  As[buf ^ 1][ac8 + 1][arow] = na0.y;\
            As[buf ^ 1][ac8 + 2][arow] = na0.z;  As[buf ^ 1][ac8 + 3][arow] = na0.w;\
            As[buf ^ 1][ac8 + 4][arow] = na1.x;  As[buf ^ 1][ac8 + 5][arow] = na1.y;\
            As[buf ^ 1][ac8 + 6][arow] = na1.z;  As[buf ^ 1][ac8 + 7][arow] = na1.w;\
            CP_WAIT0();                                                             \
            __syncthreads();                                                        \
            buf ^= 1;                                                               \
            _Pragma("unroll")                                                       \
            for (int i = 0; i < 8; i++) af[0][i] = As[buf][0][ty * 8 + i];          \
            _Pragma("unroll")                                                       \
            for (int j = 0; j < 8; j++) bf[0][j] = Bs[buf][0][tx * 8 + j];          \
        }                                                                           \
    }

// ---------------------------------------------------------------------------
// GEMM1 split-K partials: z = (pair p, qslice). K slice of x[b] @ W1[e].
// Raw fp32 partial -> g_h1p. grid 24 x 4 x 48 = 4608 CTAs (97.3% fill).
// ---------------------------------------------------------------------------
__global__ void __launch_bounds__(256, 2)
gemm1p_kernel(const float* __restrict__ X,
              const float* __restrict__ W1) {
    int z = blockIdx.z;
    int p = z / KS1;
    int q = z % KS1;
    int b = p >> 1;
    int e = g_sel[b][p & 1];
    const int kbase = q * KH1;

    const float* A  = X  + (size_t)b * SQ * HQ + kbase;
    const float* Bm = W1 + (size_t)e * HQ * FQ + (size_t)kbase * FQ;

    __shared__ float As[2][BK][BM + 4];
    __shared__ float Bs[2][BK][BN + 4];

    int tid = threadIdx.x;
    int tx = tid & 15, ty = tid >> 4;
    int m0 = blockIdx.y * BM, n0 = blockIdx.x * BN;
    int arow = tid >> 1,  ac8 = (tid & 1) * 8;
    int brow = tid >> 4,  bc  = (tid & 15) * 8;

    float acc[8][8];
#pragma unroll
    for (int i = 0; i < 8; i++)
#pragma unroll
        for (int j = 0; j < 8; j++) acc[i][j] = 0.f;

    GEMM_MAINLOOP(A, Bm, HQ, FQ, KH1)

    float* P = &g_h1p[p][q][0][0];
#pragma unroll
    for (int i = 0; i < 8; i++) {
        int row = m0 + ty * 8 + i;
        int col = n0 + tx * 8;
        float4 v0 = make_float4(acc[i][0], acc[i][1], acc[i][2], acc[i][3]);
        float4 v1 = make_float4(acc[i][4], acc[i][5], acc[i][6], acc[i][7]);
        *(float4*)&P[(size_t)row * FQ + col]     = v0;
        *(float4*)&P[(size_t)row * FQ + col + 4] = v1;
    }
}

// ---------------------------------------------------------------------------
// Reduce1: g_h = gelu( (p0+p1)+p2 + b1[e] )   (fixed order, deterministic)
// ---------------------------------------------------------------------------
__global__ void reduce1_kernel(const float* __restrict__ b1) {
    int i4 = blockIdx.x * blockDim.x + threadIdx.x;      // over 16*S*F/4
    const int per_p = SQ * FQ / 4;
    int p = i4 / per_p;
    int r = i4 % per_p;
    int col = (r * 4) % FQ;
    int e = g_sel[p >> 1][p & 1];

    const float4* P = (const float4*)&g_h1p[0][0][0][0];
    size_t base = (size_t)p * KS1 * per_p + r;
    float4 s0 = P[base];
    float4 s1 = P[base + per_p];
    float4 s2 = P[base + 2 * (size_t)per_p];
    const float* bi = b1 + (size_t)e * FQ + col;

    float4 o;
    o.x = gelu_exact((s0.x + s1.x) + s2.x + bi[0]);
    o.y = gelu_exact((s0.y + s1.y) + s2.y + bi[1]);
    o.z = gelu_exact((s0.z + s1.z) + s2.z + bi[2]);
    o.w = gelu_exact((s0.w + s1.w) + s2.w + bi[3]);
    ((float4*)&g_h[0][0][0])[i4] = o;
}

// ---------------------------------------------------------------------------
// GEMM2 split-K partials: q = (ex, kslice) in 0..5 per batch.
//   g_part[b][q] = w_ex * ( g_h[b,ex][:, kr] @ W2[e_ex][kr, :] )
// grid 6 x 4 x 48 = 1152 CTAs (97.3% fill).
// ---------------------------------------------------------------------------
__global__ void __launch_bounds__(256, 2)
gemm2p_kernel(const float* __restrict__ W2) {
    int z = blockIdx.z;
    int b = z / (2 * KS2);
    int q = z % (2 * KS2);
    int ex = q & 1;
    int ks = q >> 1;
    const int kbase = ks * KH2;

    int   e = g_sel[b][ex];
    float w = g_wsel[b][ex];
    const float* A  = &g_h[b * KQ + ex][0][0] + kbase;
    const float* Bm = W2 + (size_t)e * FQ * HQ + (size_t)kbase * HQ;

    __shared__ float As[2][BK][BM + 4];
    __shared__ float Bs[2][BK][BN + 4];

    int tid = threadIdx.x;
    int tx = tid & 15, ty = tid >> 4;
    int m0 = blockIdx.y * BM, n0 = blockIdx.x * BN;
    int arow = tid >> 1,  ac8 = (tid & 1) * 8;
    int brow = tid >> 4,  bc  = (tid & 15) * 8;

    float acc[8][8];
#pragma unroll
    for (int i = 0; i < 8; i++)
#pragma unroll
        for (int j = 0; j < 8; j++) acc[i][j] = 0.f;

    GEMM_MAINLOOP(A, Bm, FQ, HQ, KH2)

    float* P = &g_part[b][q][0][0];
#pragma unroll
    for (int i = 0; i < 8; i++) {
        int row = m0 + ty * 8 + i;
        int col = n0 + tx * 8;
        float4 v0 = make_float4(w * acc[i][0], w * acc[i][1], w * acc[i][2], w * acc[i][3]);
        float4 v1 = make_float4(w * acc[i][4], w * acc[i][5], w * acc[i][6], w * acc[i][7]);
        *(float4*)&P[(size_t)row * HQ + col]     = v0;
        *(float4*)&P[(size_t)row * HQ + col + 4] = v1;
    }
}

// ---------------------------------------------------------------------------
// Reduce2: out = sum of 6 partials + w0*b2[e0] + w1*b2[e1]  (fixed order)
// ---------------------------------------------------------------------------
__global__ void reduce2_kernel(const float* __restrict__ b2,
                               float* __restrict__ out) {
    int i4 = blockIdx.x * blockDim.x + threadIdx.x;      // over B*S*H/4
    const int per_b = SQ * HQ / 4;
    int b = i4 / per_b;
    int r = i4 % per_b;
    int col = (r * 4) % HQ;

    const float4* P = (const float4*)&g_part[0][0][0][0];
    size_t base = (size_t)b * (2 * KS2) * per_b + r;
    float4 s0 = P[base];
    float4 s1 = P[base + per_b];
    float4 s2 = P[base + 2 * (size_t)per_b];
    float4 s3 = P[base + 3 * (size_t)per_b];
    float4 s4 = P[base + 4 * (size_t)per_b];
    float4 s5 = P[base + 5 * (size_t)per_b];

    int   e0 = g_sel[b][0],  e1 = g_sel[b][1];
    float w0 = g_wsel[b][0], w1 = g_wsel[b][1];
    const float* c0 = b2 + (size_t)e0 * HQ + col;
    const float* c1 = b2 + (size_t)e1 * HQ + col;

    float4 o;
    o.x = ((s0.x + s1.x) + (s2.x + s3.x)) + (s4.x + s5.x) + w0 * c0[0] + w1 * c1[0];
    o.y = ((s0.y + s1.y) + (s2.y + s3.y)) + (s4.y + s5.y) + w0 * c0[1] + w1 * c1[1];
    o.z = ((s0.z + s1.z) + (s2.z + s3.z)) + (s4.z + s5.z) + w0 * c0[2] + w1 * c1[2];
    o.w = ((s0.w + s1.w) + (s2.w + s3.w)) + (s4.w + s5.w) + w0 * c0[3] + w1 * c1[3];
    ((float4*)out)[i4] = o;
}

// ---------------------------------------------------------------------------
// Launch: xbar1/2 -> router -> gemm1 partials -> reduce1(+gelu)
//         -> gemm2 partials -> reduce2
// Output layout: [ final (B*S*H) | router_logits (B*E) ]
// ---------------------------------------------------------------------------
extern "C" void kernel_launch(void* const* d_in, const int* in_sizes, int n_in,
                              void* d_out, int out_size) {
    const float* x  = (const float*)d_in[0];
    const float* Wg = (const float*)d_in[1];
    const float* W1 = (const float*)d_in[2];
    const float* b1 = (const float*)d_in[3];
    const float* W2 = (const float*)d_in[4];
    const float* b2 = (const float*)d_in[5];
    float* out = (float*)d_out;
    float* out_logits = out + (size_t)BQ * SQ * HQ;

    xbar1_kernel<<<BQ * 8, HQ>>>(x);
    xbar2_kernel<<<BQ, HQ>>>();
    router_kernel<<<1, 64>>>(Wg, out_logits);
    gemm1p_kernel<<<dim3(FQ / BN, SQ / BM, BQ * KQ * KS1), 256>>>(x, W1);
    reduce1_kernel<<<(BQ * KQ * SQ * FQ / 4) / 256, 256>>>(b1);
    gemm2p_kernel<<<dim3(HQ / BN, SQ / BM, BQ * 2 * KS2), 256>>>(W2);
    reduce2_kernel<<<(BQ * SQ * HQ / 4) / 256, 256>>>(b2, out);
}

// round 16
// speedup vs baseline: 1.4735x; 1.1075x over previous
#include <cuda_runtime.h>
#include <math.h>

// Problem dims
#define BQ 8
#define SQ 512
#define HQ 768
#define EQ 8
#define FQ 3072
#define KQ 2

// GEMM tiling
#define BM 128
#define BN 128
#define BK 16

// K-splits
#define KS1 3              // gemm1: 768 = 3 x 256
#define KH1 (HQ / KS1)     // 256
#define KS2 3              // gemm2: 3072 = 3 x 1024 (per expert)
#define KH2 (FQ / KS2)     // 1024

// Scratch / routing state (static device memory: allocation-free, graph-safe)
__device__ float g_xpart[BQ][8][HQ];                  // xbar partials
__device__ float g_xbar[BQ][HQ];
__device__ int   g_sel[BQ][KQ];
__device__ float g_wsel[BQ][KQ];
__device__ float g_h1p[BQ * KQ][KS1][SQ][FQ];         // gemm1 raw partials (~302 MB)
__device__ float g_h[BQ * KQ][SQ][FQ];                // gelu(x@W1+b1) (~100 MB)
__device__ float g_part[BQ][2 * KS2][SQ][HQ];         // gemm2 partials (~75 MB)

__device__ __forceinline__ float gelu_exact(float v) {
    return 0.5f * v * (1.0f + erff(v * 0.70710678118654752f));
}
__device__ __forceinline__ void cp16(void* sdst, const void* gsrc) {
    unsigned d = (unsigned)__cvta_generic_to_shared(sdst);
    asm volatile("cp.async.cg.shared.global [%0], [%1], 16;\n" :: "r"(d), "l"(gsrc));
}
#define CP_COMMIT() asm volatile("cp.async.commit_group;\n" ::)
#define CP_WAIT0()  asm volatile("cp.async.wait_group 0;\n" ::)

// ---------------------------------------------------------------------------
// xbar stage 1: 64 CTAs, each sums 64 seq rows -> g_xpart[b][chunk][h]
// ---------------------------------------------------------------------------
__global__ void xbar1_kernel(const float* __restrict__ x) {
    int b = blockIdx.x >> 3;
    int c = blockIdx.x & 7;
    int h = threadIdx.x;
    const float* p = x + (size_t)b * SQ * HQ + (size_t)c * 64 * HQ + h;
    float s = 0.f;
#pragma unroll 8
    for (int i = 0; i < 64; i++) s += p[(size_t)i * HQ];
    g_xpart[b][c][h] = s;
}

// xbar stage 2: fold 8 partials
__global__ void xbar2_kernel() {
    int b = blockIdx.x;
    int h = threadIdx.x;
    float s = 0.f;
#pragma unroll
    for (int c = 0; c < 8; c++) s += g_xpart[b][c][h];
    g_xbar[b][h] = s * (1.0f / SQ);
}

// ---------------------------------------------------------------------------
// Router: logits[b,e] = xbar[b] . Wg[:,e]; softmax over E; top-2 select.
// ---------------------------------------------------------------------------
__global__ void router_kernel(const float* __restrict__ Wg,
                              float* __restrict__ out_logits) {
    __shared__ float lg[BQ][EQ];
    int t = threadIdx.x;
    if (t < BQ * EQ) {
        int b = t / EQ, e = t % EQ;
        float s = 0.f;
        for (int h = 0; h < HQ; h++) s += g_xbar[b][h] * Wg[h * EQ + e];
        lg[b][e] = s;
        out_logits[b * EQ + e] = s;
    }
    __syncthreads();
    if (t < BQ) {
        int b = t;
        float m = -1e30f;
        for (int e = 0; e < EQ; e++) m = fmaxf(m, lg[b][e]);
        float w[EQ];
        float s = 0.f;
        for (int e = 0; e < EQ; e++) { w[e] = expf(lg[b][e] - m); s += w[e]; }
        float inv = 1.f / s;
        for (int e = 0; e < EQ; e++) w[e] *= inv;
        int i1 = 0;
        for (int e = 1; e < EQ; e++) if (w[e] > w[i1]) i1 = e;
        int i2 = -1;
        for (int e = 0; e < EQ; e++) {
            if (e == i1) continue;
            if (i2 < 0 || w[e] > w[i2]) i2 = e;
        }
        g_sel[b][0] = i1;  g_sel[b][1] = i2;
        g_wsel[b][0] = w[i1]; g_wsel[b][1] = w[i2];
    }
}

// ---------------------------------------------------------------------------
// Pipelined GEMM mainloop. Quadrant microtile (2x2 blocks of 4x4):
//   rows {ty*4..+3, 64+ty*4..+3}, cols {tx*4..+3, 64+tx*4..+3}
// Fragment LDS are float4 at lane-contiguous addresses -> conflict-free.
// Software-pipelined fragments (LDS for kq+1 before FMAs of kq).
// ---------------------------------------------------------------------------
#define LD_FRAG(dst, kqv)                                                           \
    do {                                                                            \
        float4 _a0 = *(const float4*)&As[buf][kqv][ty * 4];                         \
        float4 _a1 = *(const float4*)&As[buf][kqv][64 + ty * 4];                    \
        float4 _b0 = *(const float4*)&Bs[buf][kqv][tx * 4];                         \
        float4 _b1 = *(const float4*)&Bs[buf][kqv][64 + tx * 4];                    \
        af[dst][0] = _a0.x; af[dst][1] = _a0.y; af[dst][2] = _a0.z; af[dst][3] = _a0.w; \
        af[dst][4] = _a1.x; af[dst][5] = _a1.y; af[dst][6] = _a1.z; af[dst][7] = _a1.w; \
        bf[dst][0] = _b0.x; bf[dst][1] = _b0.y; bf[dst][2] = _b0.z; bf[dst][3] = _b0.w; \
        bf[dst][4] = _b1.x; bf[dst][5] = _b1.y; bf[dst][6] = _b1.z; bf[dst][7] = _b1.w; \
    } while (0)

#define GEMM_MAINLOOP(Aptr, Bptr, LDA, LDB, KLEN)                                   \
    {                                                                               \
        const float* ap0 = (Aptr) + (size_t)(m0 + arow) * (LDA) + ac8;              \
        float4 a0 = *(const float4*)ap0;                                            \
        float4 a1 = *(const float4*)(ap0 + 4);                                      \
        As[0][ac8 + 0][arow] = a0.x;  As[0][ac8 + 1][arow] = a0.y;                  \
        As[0][ac8 + 2][arow] = a0.z;  As[0][ac8 + 3][arow] = a0.w;                  \
        As[0][ac8 + 4][arow] = a1.x;  As[0][ac8 + 5][arow] = a1.y;                  \
        As[0][ac8 + 6][arow] = a1.z;  As[0][ac8 + 7][arow] = a1.w;                  \
        const float* bp0 = (Bptr) + (size_t)brow * (LDB) + n0 + bc;                 \
        cp16(&Bs[0][brow][bc], bp0);                                                \
        cp16(&Bs[0][brow][bc + 4], bp0 + 4);                                        \
        CP_COMMIT();                                                                \
        CP_WAIT0();                                                                 \
        __syncthreads();                                                            \
    }                                                                               \
    int buf = 0;                                                                    \
    const int NT = (KLEN) / BK;                                                     \
    float af[2][8], bf[2][8];                                                       \
    LD_FRAG(0, 0);                                                                  \
    for (int kt = 0; kt < NT; kt++) {                                               \
        float4 na0, na1;                                                            \
        const bool more = (kt + 1) < NT;                                            \
        if (more) {                                                                 \
            const float* ap = (Aptr) + (size_t)(m0 + arow) * (LDA)                  \
                              + (kt + 1) * BK + ac8;                                \
            na0 = *(const float4*)ap;                                               \
            na1 = *(const float4*)(ap + 4);                                         \
            const float* bp = (Bptr) + (size_t)((kt + 1) * BK + brow) * (LDB)       \
                              + n0 + bc;                                            \
            cp16(&Bs[buf ^ 1][brow][bc], bp);                                       \
            cp16(&Bs[buf ^ 1][brow][bc + 4], bp + 4);                               \
            CP_COMMIT();                                                            \
        }                                                                           \
        _Pragma("unroll")                                                           \
        for (int kq = 0; kq < BK; kq++) {                                           \
            int cur = kq & 1, nxt = cur ^ 1;                                        \
            if (kq + 1 < BK) LD_FRAG(nxt, kq + 1);                                  \
            _Pragma("unroll")                                                       \
            for (int i = 0; i < 8; i++)                                             \
                _Pragma("unroll")                                                   \
                for (int j = 0; j < 8; j++)                                         \
                    acc[i][j] = fmaf(af[cur][i], bf[cur][j], acc[i][j]);            \
        }                                                                           \
        if (more) {                                                                 \
            As[buf ^ 1][ac8 + 0][arow] = na0.x;  As[buf ^ 1][ac8 + 1][arow] = na0.y;\
            As[buf ^ 1][ac8 + 2][arow] = na0.z;  As[buf ^ 1][ac8 + 3][arow] = na0.w;\
            As[buf ^ 1][ac8 + 4][arow] = na1.x;  As[buf ^ 1][ac8 + 5][arow] = na1.y;\
            As[buf ^ 1][ac8 + 6][arow] = na1.z;  As[buf ^ 1][ac8 + 7][arow] = na1.w;\
            CP_WAIT0();                                                             \
            __syncthreads();                                                        \
            buf ^= 1;                                                               \
            LD_FRAG(0, 0);                                                          \
        }                                                                           \
    }

// Quadrant epilogue row/col helpers: ri -> global row offset, j-quadrant -> col
#define QROW(i) ((i) < 4 ? ty * 4 + (i) : 64 + ty * 4 + (i) - 4)

// ---------------------------------------------------------------------------
// GEMM1 split-K partials: z = (pair p, qslice). K slice of x[b] @ W1[e].
// Raw fp32 partial -> g_h1p. grid 24 x 4 x 48 = 4608 CTAs (97.3% fill).
// ---------------------------------------------------------------------------
__global__ void __launch_bounds__(256, 2)
gemm1p_kernel(const float* __restrict__ X,
              const float* __restrict__ W1) {
    int z = blockIdx.z;
    int p = z / KS1;
    int q = z % KS1;
    int b = p >> 1;
    int e = g_sel[b][p & 1];
    const int kbase = q * KH1;

    const float* A  = X  + (size_t)b * SQ * HQ + kbase;
    const float* Bm = W1 + (size_t)e * HQ * FQ + (size_t)kbase * FQ;

    __shared__ float As[2][BK][BM + 4];
    __shared__ float Bs[2][BK][BN + 4];

    int tid = threadIdx.x;
    int tx = tid & 15, ty = tid >> 4;
    int m0 = blockIdx.y * BM, n0 = blockIdx.x * BN;
    int arow = tid >> 1,  ac8 = (tid & 1) * 8;
    int brow = tid >> 4,  bc  = (tid & 15) * 8;

    float acc[8][8];
#pragma unroll
    for (int i = 0; i < 8; i++)
#pragma unroll
        for (int j = 0; j < 8; j++) acc[i][j] = 0.f;

    GEMM_MAINLOOP(A, Bm, HQ, FQ, KH1)

    float* P = &g_h1p[p][q][0][0];
#pragma unroll
    for (int i = 0; i < 8; i++) {
        int row = m0 + QROW(i);
        float4 v0 = make_float4(acc[i][0], acc[i][1], acc[i][2], acc[i][3]);
        float4 v1 = make_float4(acc[i][4], acc[i][5], acc[i][6], acc[i][7]);
        *(float4*)&P[(size_t)row * FQ + n0 + tx * 4]      = v0;
        *(float4*)&P[(size_t)row * FQ + n0 + 64 + tx * 4] = v1;
    }
}

// ---------------------------------------------------------------------------
// Reduce1: g_h = gelu( (p0+p1)+p2 + b1[e] )   (fixed order, deterministic)
// ---------------------------------------------------------------------------
__global__ void reduce1_kernel(const float* __restrict__ b1) {
    int i4 = blockIdx.x * blockDim.x + threadIdx.x;      // over 16*S*F/4
    const int per_p = SQ * FQ / 4;
    int p = i4 / per_p;
    int r = i4 % per_p;
    int col = (r * 4) % FQ;
    int e = g_sel[p >> 1][p & 1];

    const float4* P = (const float4*)&g_h1p[0][0][0][0];
    size_t base = (size_t)p * KS1 * per_p + r;
    float4 s0 = P[base];
    float4 s1 = P[base + per_p];
    float4 s2 = P[base + 2 * (size_t)per_p];
    const float* bi = b1 + (size_t)e * FQ + col;

    float4 o;
    o.x = gelu_exact((s0.x + s1.x) + s2.x + bi[0]);
    o.y = gelu_exact((s0.y + s1.y) + s2.y + bi[1]);
    o.z = gelu_exact((s0.z + s1.z) + s2.z + bi[2]);
    o.w = gelu_exact((s0.w + s1.w) + s2.w + bi[3]);
    ((float4*)&g_h[0][0][0])[i4] = o;
}

// ---------------------------------------------------------------------------
// GEMM2 split-K partials: q = (ex, kslice) in 0..5 per batch.
//   g_part[b][q] = w_ex * ( g_h[b,ex][:, kr] @ W2[e_ex][kr, :] )
// grid 6 x 4 x 48 = 1152 CTAs (97.3% fill).
// ---------------------------------------------------------------------------
__global__ void __launch_bounds__(256, 2)
gemm2p_kernel(const float* __restrict__ W2) {
    int z = blockIdx.z;
    int b = z / (2 * KS2);
    int q = z % (2 * KS2);
    int ex = q & 1;
    int ks = q >> 1;
    const int kbase = ks * KH2;

    int   e = g_sel[b][ex];
    float w = g_wsel[b][ex];
    const float* A  = &g_h[b * KQ + ex][0][0] + kbase;
    const float* Bm = W2 + (size_t)e * FQ * HQ + (size_t)kbase * HQ;

    __shared__ float As[2][BK][BM + 4];
    __shared__ float Bs[2][BK][BN + 4];

    int tid = threadIdx.x;
    int tx = tid & 15, ty = tid >> 4;
    int m0 = blockIdx.y * BM, n0 = blockIdx.x * BN;
    int arow = tid >> 1,  ac8 = (tid & 1) * 8;
    int brow = tid >> 4,  bc  = (tid & 15) * 8;

    float acc[8][8];
#pragma unroll
    for (int i = 0; i < 8; i++)
#pragma unroll
        for (int j = 0; j < 8; j++) acc[i][j] = 0.f;

    GEMM_MAINLOOP(A, Bm, FQ, HQ, KH2)

    float* P = &g_part[b][q][0][0];
#pragma unroll
    for (int i = 0; i < 8; i++) {
        int row = m0 + QROW(i);
        float4 v0 = make_float4(w * acc[i][0], w * acc[i][1], w * acc[i][2], w * acc[i][3]);
        float4 v1 = make_float4(w * acc[i][4], w * acc[i][5], w * acc[i][6], w * acc[i][7]);
        *(float4*)&P[(size_t)row * HQ + n0 + tx * 4]      = v0;
        *(float4*)&P[(size_t)row * HQ + n0 + 64 + tx * 4] = v1;
    }
}

// ---------------------------------------------------------------------------
// Reduce2: out = sum of 6 partials + w0*b2[e0] + w1*b2[e1]  (fixed order)
// ---------------------------------------------------------------------------
__global__ void reduce2_kernel(const float* __restrict__ b2,
                               float* __restrict__ out) {
    int i4 = blockIdx.x * blockDim.x + threadIdx.x;      // over B*S*H/4
    const int per_b = SQ * HQ / 4;
    int b = i4 / per_b;
    int r = i4 % per_b;
    int col = (r * 4) % HQ;

    const float4* P = (const float4*)&g_part[0][0][0][0];
    size_t base = (size_t)b * (2 * KS2) * per_b + r;
    float4 s0 = P[base];
    float4 s1 = P[base + per_b];
    float4 s2 = P[base + 2 * (size_t)per_b];
    float4 s3 = P[base + 3 * (size_t)per_b];
    float4 s4 = P[base + 4 * (size_t)per_b];
    float4 s5 = P[base + 5 * (size_t)per_b];

    int   e0 = g_sel[b][0],  e1 = g_sel[b][1];
    float w0 = g_wsel[b][0], w1 = g_wsel[b][1];
    const float* c0 = b2 + (size_t)e0 * HQ + col;
    const float* c1 = b2 + (size_t)e1 * HQ + col;

    float4 o;
    o.x = ((s0.x + s1.x) + (s2.x + s3.x)) + (s4.x + s5.x) + w0 * c0[0] + w1 * c1[0];
    o.y = ((s0.y + s1.y) + (s2.y + s3.y)) + (s4.y + s5.y) + w0 * c0[1] + w1 * c1[1];
    o.z = ((s0.z + s1.z) + (s2.z + s3.z)) + (s4.z + s5.z) + w0 * c0[2] + w1 * c1[2];
    o.w = ((s0.w + s1.w) + (s2.w + s3.w)) + (s4.w + s5.w) + w0 * c0[3] + w1 * c1[3];
    ((float4*)out)[i4] = o;
}

// ---------------------------------------------------------------------------
// Launch: xbar1/2 -> router -> gemm1 partials -> reduce1(+gelu)
//         -> gemm2 partials -> reduce2
// Output layout: [ final (B*S*H) | router_logits (B*E) ]
// ---------------------------------------------------------------------------
extern "C" void kernel_launch(void* const* d_in, const int* in_sizes, int n_in,
                              void* d_out, int out_size) {
    const float* x  = (const float*)d_in[0];
    const float* Wg = (const float*)d_in[1];
    const float* W1 = (const float*)d_in[2];
    const float* b1 = (const float*)d_in[3];
    const float* W2 = (const float*)d_in[4];
    const float* b2 = (const float*)d_in[5];
    float* out = (float*)d_out;
    float* out_logits = out + (size_t)BQ * SQ * HQ;

    xbar1_kernel<<<BQ * 8, HQ>>>(x);
    xbar2_kernel<<<BQ, HQ>>>();
    router_kernel<<<1, 64>>>(Wg, out_logits);
    gemm1p_kernel<<<dim3(FQ / BN, SQ / BM, BQ * KQ * KS1), 256>>>(x, W1);
    reduce1_kernel<<<(BQ * KQ * SQ * FQ / 4) / 256, 256>>>(b1);
    gemm2p_kernel<<<dim3(HQ / BN, SQ / BM, BQ * 2 * KS2), 256>>>(W2);
    reduce2_kernel<<<(BQ * SQ * HQ / 4) / 256, 256>>>(b2, out);
}